// round 8
// baseline (speedup 1.0000x reference)
#include <cuda_runtime.h>
#include <cuda_bf16.h>
#include <math.h>
#include <stdint.h>

// Problem constants
#define BATCH 2
#define SEQ   2048
#define CDIM  2048
#define NHEAD 16
#define NKV   4
#define HDIM  128
#define HALF  64
#define MROWS (BATCH*SEQ)          // 4096
#define QW    (NHEAD*HDIM)         // 2048
#define KW    (NKV*HDIM)           // 512

// ---------------------------------------------------------------------------
// Scratch (device globals; no allocations allowed)
// ---------------------------------------------------------------------------
__device__ __nv_bfloat16 g_x2  [4096 * 4096];     // 32 MB (x split; later attn-out split)
__device__ __nv_bfloat16 g_wqkv[3072 * 4096];     // 24 MB packed [Wq|Wk|Wv] transposed split
__device__ __nv_bfloat16 g_wo2 [2048 * 4096];     // 16 MB
__device__ __nv_bfloat16 g_qh[MROWS * QW];        // 16 MB
__device__ __nv_bfloat16 g_ql[MROWS * QW];        // 16 MB
__device__ __nv_bfloat16 g_kh[MROWS * KW];        // 4 MB
__device__ __nv_bfloat16 g_kl[MROWS * KW];        // 4 MB
__device__ __nv_bfloat16 g_vh[MROWS * KW];        // 4 MB
__device__ __nv_bfloat16 g_vl[MROWS * KW];        // 4 MB

// ---------------------------------------------------------------------------
// Baseline-PTX tensor-core helpers
// ---------------------------------------------------------------------------
__device__ __forceinline__ uint32_t smem_u32_of(const void* p) {
    uint32_t a;
    asm("{ .reg .u64 t; cvta.to.shared.u64 t, %1; cvt.u32.u64 %0, t; }" : "=r"(a) : "l"(p));
    return a;
}
__device__ __forceinline__ void cp_async16(uint32_t saddr, const void* gaddr) {
    asm volatile("cp.async.cg.shared.global [%0], [%1], 16;" :: "r"(saddr), "l"(gaddr));
}
__device__ __forceinline__ void cp_commit() {
    asm volatile("cp.async.commit_group;" ::: "memory");
}
__device__ __forceinline__ void cp_wait1() {
    asm volatile("cp.async.wait_group 1;" ::: "memory");
}
__device__ __forceinline__ void cp_wait0() {
    asm volatile("cp.async.wait_group 0;" ::: "memory");
}
__device__ __forceinline__ void ldmatrix_x4(uint32_t* r, uint32_t addr) {
    asm volatile("ldmatrix.sync.aligned.m8n8.x4.shared.b16 {%0,%1,%2,%3}, [%4];"
                 : "=r"(r[0]), "=r"(r[1]), "=r"(r[2]), "=r"(r[3]) : "r"(addr));
}
__device__ __forceinline__ void ldmatrix_x4_trans(uint32_t* r, uint32_t addr) {
    asm volatile("ldmatrix.sync.aligned.m8n8.x4.trans.shared.b16 {%0,%1,%2,%3}, [%4];"
                 : "=r"(r[0]), "=r"(r[1]), "=r"(r[2]), "=r"(r[3]) : "r"(addr));
}
__device__ __forceinline__ void mma_bf16(float* c, const uint32_t* a, uint32_t b0, uint32_t b1) {
    asm volatile(
        "mma.sync.aligned.m16n8k16.row.col.f32.bf16.bf16.f32 "
        "{%0,%1,%2,%3}, {%4,%5,%6,%7}, {%8,%9}, {%0,%1,%2,%3};"
        : "+f"(c[0]), "+f"(c[1]), "+f"(c[2]), "+f"(c[3])
        : "r"(a[0]), "r"(a[1]), "r"(a[2]), "r"(a[3]), "r"(b0), "r"(b1));
}

// swizzled smem offsets (16B chunks, XOR row&7)
#define SW256(r, c) ((uint32_t)((r) * 256 + (((c) ^ ((r) & 7)) << 4)))
#define SW128(r, c) ((uint32_t)((r) * 128 + (((c) ^ ((r) & 7)) << 4)))

// bf16 hi/lo split store of 2 consecutive values
__device__ __forceinline__ void split_store2(__nv_bfloat16* oh, __nv_bfloat16* ol,
                                             size_t idx, float a, float b) {
    __nv_bfloat16 h0 = __float2bfloat16(a), h1 = __float2bfloat16(b);
    __nv_bfloat162 hp = {h0, h1};
    __nv_bfloat162 lp = {__float2bfloat16(a - __bfloat162float(h0)),
                         __float2bfloat16(b - __bfloat162float(h1))};
    *reinterpret_cast<__nv_bfloat162*>(oh + idx) = hp;
    *reinterpret_cast<__nv_bfloat162*>(ol + idx) = lp;
}

// ===========================================================================
// GEMM core: 128x128 CTA tile, BK=64, 3-stage cp.async pipeline.
// A2[M,4096]=[hi|lo] K-major, B2[N,4096]=[hi|lo] K-major; 3 K-segments.
// ===========================================================================
#define HG_SMEM (3 * 32768)
#define HG_NIT  96

struct GemmFrag { float acc[4][4][4]; };

__device__ __forceinline__ void gemm_mainloop(
    const __nv_bfloat16* __restrict__ A2, const __nv_bfloat16* __restrict__ B2,
    uint32_t su, int m0, int n0, GemmFrag& F)
{
    const int tid  = threadIdx.x;
    const int wid  = tid >> 5;
    const int lane = tid & 31;
    const int ld = 4096;

    uint32_t smoff[4];
    const __nv_bfloat16 *gA[4], *gB[4];
#pragma unroll
    for (int i = 0; i < 4; i++) {
        int id = tid + i * 256;
        int r = id >> 3, c = id & 7;
        smoff[i] = (uint32_t)(r * 128 + ((c ^ (r & 7)) << 4));
        gA[i] = A2 + (size_t)(m0 + r) * ld + c * 8;
        gB[i] = B2 + (size_t)(n0 + r) * ld + c * 8;
    }

    const int mwarp = (wid >> 2) * 64;
    const int nwarp = (wid & 3) * 32;

    const int asel = lane >> 3;
    const int arow = (lane & 7) + ((asel & 1) << 3);
    const int akc  = asel >> 1;
    const int brow = (lane & 7) + ((asel >> 1) << 3);
    const int bkc  = asel & 1;

#pragma unroll
    for (int mf = 0; mf < 4; mf++)
#pragma unroll
        for (int nf = 0; nf < 4; nf++)
#pragma unroll
            for (int e = 0; e < 4; e++) F.acc[mf][nf][e] = 0.f;

    auto issue = [&](int it, int stage) {
        int seg = it >> 5;
        int t   = it & 31;
        int aoff = t * 64 + (seg == 1 ? 2048 : 0);
        int boff = t * 64 + (seg == 2 ? 2048 : 0);
        uint32_t ab = su + (uint32_t)stage * 32768u;
        uint32_t bb = ab + 16384u;
#pragma unroll
        for (int i = 0; i < 4; i++) {
            cp_async16(ab + smoff[i], gA[i] + aoff);
            cp_async16(bb + smoff[i], gB[i] + boff);
        }
        cp_commit();
    };

    issue(0, 0);
    issue(1, 1);

    int sCur = 0, sNxt = 2;
    for (int it = 0; it < HG_NIT; ++it) {
        if (it + 1 < HG_NIT) cp_wait1();
        else                 cp_wait0();
        __syncthreads();
        if (it + 2 < HG_NIT) issue(it + 2, sNxt);

        uint32_t abase = su + (uint32_t)sCur * 32768u;
        uint32_t bbase = abase + 16384u;

#pragma unroll
        for (int ks = 0; ks < 4; ++ks) {
            uint32_t ar[4][4];
#pragma unroll
            for (int mf = 0; mf < 4; mf++) {
                int R = mwarp + mf * 16 + arow;
                int ch = ks * 2 + akc;
                ldmatrix_x4(ar[mf], abase + R * 128 + (uint32_t)((ch ^ (R & 7)) << 4));
            }
            uint32_t br[2][4];
#pragma unroll
            for (int bh = 0; bh < 2; bh++) {
                int R = nwarp + bh * 16 + brow;
                int ch = ks * 2 + bkc;
                ldmatrix_x4(br[bh], bbase + R * 128 + (uint32_t)((ch ^ (R & 7)) << 4));
            }
#pragma unroll
            for (int mf = 0; mf < 4; mf++) {
#pragma unroll
                for (int bh = 0; bh < 2; bh++) {
                    mma_bf16(F.acc[mf][bh * 2 + 0], ar[mf], br[bh][0], br[bh][1]);
                    mma_bf16(F.acc[mf][bh * 2 + 1], ar[mf], br[bh][2], br[bh][3]);
                }
            }
        }
        sCur = (sCur == 2) ? 0 : sCur + 1;
        sNxt = (sNxt == 2) ? 0 : sNxt + 1;
    }
}

// ---------------------------------------------------------------------------
// Generic GEMM with fp32 output + optional bias (used for Wo).
// ---------------------------------------------------------------------------
__global__ __launch_bounds__(256, 1)
void hgemm_kernel(const __nv_bfloat16* __restrict__ A2, const __nv_bfloat16* __restrict__ B2,
                  float* __restrict__ C, int N, const float* __restrict__ bias)
{
    extern __shared__ __align__(1024) char smem[];
    const uint32_t su = smem_u32_of(smem);
    const int tid  = threadIdx.x;
    const int wid  = tid >> 5;
    const int lane = tid & 31;
    const int m0 = blockIdx.y * 128;
    const int n0 = blockIdx.x * 128;

    GemmFrag F;
    gemm_mainloop(A2, B2, su, m0, n0, F);

    const int mwarp = (wid >> 2) * 64;
    const int nwarp = (wid & 3) * 32;
    const int mrow = lane >> 2;
    const int ncol = (lane & 3) * 2;
#pragma unroll
    for (int mf = 0; mf < 4; mf++) {
#pragma unroll
        for (int nf = 0; nf < 4; nf++) {
            int gm = m0 + mwarp + mf * 16 + mrow;
            int gn = n0 + nwarp + nf * 8 + ncol;
            float b0 = 0.f, b1 = 0.f;
            if (bias != nullptr) { b0 = bias[gn]; b1 = bias[gn + 1]; }
            float2 lo = make_float2(F.acc[mf][nf][0] + b0, F.acc[mf][nf][1] + b1);
            float2 hi = make_float2(F.acc[mf][nf][2] + b0, F.acc[mf][nf][3] + b1);
            *reinterpret_cast<float2*>(C + (size_t)gm * N + gn)       = lo;
            *reinterpret_cast<float2*>(C + (size_t)(gm + 8) * N + gn) = hi;
        }
    }
}

// ---------------------------------------------------------------------------
// Fused QKV GEMM + per-head RMSNorm + RoPE + bf16 split epilogue.
//   cols [0,2048)    -> q heads: rmsnorm+rope -> qh/ql
//   cols [2048,2560) -> k heads: rmsnorm+rope -> kh/kl
//   cols [2560,3072) -> v: plain bf16 hi/lo split -> vh/vl
// Each 128-col N-tile is exactly one head (q) or one kv head (k/v).
// ---------------------------------------------------------------------------
__global__ __launch_bounds__(256, 1)
void qkv_gemm_kernel(const __nv_bfloat16* __restrict__ A2, const __nv_bfloat16* __restrict__ B2,
                     const float* __restrict__ cosp, const float* __restrict__ sinp,
                     __nv_bfloat16* __restrict__ qh, __nv_bfloat16* __restrict__ ql,
                     __nv_bfloat16* __restrict__ kh, __nv_bfloat16* __restrict__ kl,
                     __nv_bfloat16* __restrict__ vh, __nv_bfloat16* __restrict__ vl)
{
    extern __shared__ __align__(1024) char smem[];
    const uint32_t su = smem_u32_of(smem);
    const int tid  = threadIdx.x;
    const int wid  = tid >> 5;
    const int lane = tid & 31;
    const int m0 = blockIdx.y * 128;
    const int n0 = blockIdx.x * 128;

    GemmFrag F;
    gemm_mainloop(A2, B2, su, m0, n0, F);

    const int mwarp = (wid >> 2) * 64;
    const int nwarp = (wid & 3) * 32;
    const int mrow = lane >> 2;
    const int ncol = (lane & 3) * 2;

    if (n0 >= 2560) {
        // V region: plain bf16 hi/lo split
#pragma unroll
        for (int mf = 0; mf < 4; mf++)
#pragma unroll
            for (int nf = 0; nf < 4; nf++) {
                int gm = m0 + mwarp + mf * 16 + mrow;
                int gn = n0 - 2560 + nwarp + nf * 8 + ncol;
                split_store2(vh, vl, (size_t)gm * 512 + gn,
                             F.acc[mf][nf][0], F.acc[mf][nf][1]);
                split_store2(vh, vl, (size_t)(gm + 8) * 512 + gn,
                             F.acc[mf][nf][2], F.acc[mf][nf][3]);
            }
        return;
    }

    // ---- Q/K region: RMSNorm + RoPE + split, all in-CTA ----
    __syncthreads();   // pipeline smem no longer needed; safe to reuse
    const int NP = 132;
    float* ntile = reinterpret_cast<float*>(smem);     // [128][132] fp32
    float* ssqp  = ntile + 128 * NP;                   // [4][128]
    float* rmsv  = ssqp + 512;                         // [128]

    // stage fp32 values + per-warp row ssq partials
#pragma unroll
    for (int mf = 0; mf < 4; mf++) {
        int lr0 = mwarp + mf * 16 + mrow;
        int lr1 = lr0 + 8;
        float p0 = 0.f, p1 = 0.f;
#pragma unroll
        for (int nf = 0; nf < 4; nf++) {
            int cc = nwarp + nf * 8 + ncol;
            float a0 = F.acc[mf][nf][0], a1 = F.acc[mf][nf][1];
            float a2 = F.acc[mf][nf][2], a3 = F.acc[mf][nf][3];
            ntile[lr0 * NP + cc]     = a0;
            ntile[lr0 * NP + cc + 1] = a1;
            ntile[lr1 * NP + cc]     = a2;
            ntile[lr1 * NP + cc + 1] = a3;
            p0 += a0 * a0 + a1 * a1;
            p1 += a2 * a2 + a3 * a3;
        }
        p0 += __shfl_xor_sync(0xffffffffu, p0, 1);
        p0 += __shfl_xor_sync(0xffffffffu, p0, 2);
        p1 += __shfl_xor_sync(0xffffffffu, p1, 1);
        p1 += __shfl_xor_sync(0xffffffffu, p1, 2);
        if ((lane & 3) == 0) {
            ssqp[(wid & 3) * 128 + lr0] = p0;
            ssqp[(wid & 3) * 128 + lr1] = p1;
        }
    }
    __syncthreads();
    if (tid < 128) {
        float s = ssqp[tid] + ssqp[128 + tid] + ssqp[256 + tid] + ssqp[384 + tid];
        rmsv[tid] = rsqrtf(s * (1.0f / 128.0f) + 1.1920929e-7f);
    }
    __syncthreads();

    // RoPE + split: 2 threads per row, 32 dims each half
    {
        int r = tid >> 1;
        int dbase = (tid & 1) * 32;
        int gm = m0 + r;
        int t  = gm & (SEQ - 1);
        float rm = rmsv[r];
        const bool isq = (n0 < 2048);
        __nv_bfloat16* oh = isq ? qh : kh;
        __nv_bfloat16* ol = isq ? ql : kl;
        size_t stride = isq ? 2048 : 512;
        int colbase = isq ? n0 : (n0 - 2048);
        size_t rowoff = (size_t)gm * stride + colbase;
        const float* crow = cosp + t * HALF;
        const float* srow = sinp + t * HALF;
        const float* nrow = ntile + r * NP;
#pragma unroll 4
        for (int j = 0; j < 32; j += 2) {
            int d = dbase + j;
            float v0a = nrow[d]      * rm, v1a = nrow[d + 64] * rm;
            float v0b = nrow[d + 1]  * rm, v1b = nrow[d + 65] * rm;
            float ca = crow[d],     sa = srow[d];
            float cb = crow[d + 1], sb = srow[d + 1];
            split_store2(oh, ol, rowoff + d,      v0a * ca - v1a * sa, v0b * cb - v1b * sb);
            split_store2(oh, ol, rowoff + 64 + d, v0a * sa + v1a * ca, v0b * sb + v1b * cb);
        }
    }
}

// ---------------------------------------------------------------------------
// fp32 -> (hi, lo) bf16 split. src [M, 2048] -> dst [M, 4096] ([hi|lo]).
// ---------------------------------------------------------------------------
__global__ void split2048_kernel(const float* __restrict__ src, __nv_bfloat16* __restrict__ dst)
{
    int i = blockIdx.x * 256 + threadIdx.x;
    float4 v = reinterpret_cast<const float4*>(src)[i];
    int e = i * 4;
    int m = e >> 11;
    int k = e & 2047;
    __nv_bfloat16* d = dst + (size_t)m * 4096 + k;
    __nv_bfloat16 h0 = __float2bfloat16(v.x), h1 = __float2bfloat16(v.y);
    __nv_bfloat16 h2 = __float2bfloat16(v.z), h3 = __float2bfloat16(v.w);
    d[0] = h0; d[1] = h1; d[2] = h2; d[3] = h3;
    d[2048] = __float2bfloat16(v.x - __bfloat162float(h0));
    d[2049] = __float2bfloat16(v.y - __bfloat162float(h1));
    d[2050] = __float2bfloat16(v.z - __bfloat162float(h2));
    d[2051] = __float2bfloat16(v.w - __bfloat162float(h3));
}

// ---------------------------------------------------------------------------
// Transposed split of W [2048, N] into dst columns [nbase, nbase+N).
// ---------------------------------------------------------------------------
__device__ __forceinline__ void tsplit_body(const float* __restrict__ W,
                                            __nv_bfloat16* __restrict__ dst,
                                            int N, int nbase, int bx, int by)
{
    __shared__ float tl[32][33];
    int tx = threadIdx.x, ty = threadIdx.y;
    int n0 = bx * 32, k0 = by * 32;
#pragma unroll
    for (int j = 0; j < 4; j++)
        tl[ty + j * 8][tx] = W[(size_t)(k0 + ty + j * 8) * N + n0 + tx];
    __syncthreads();
#pragma unroll
    for (int j = 0; j < 4; j++) {
        int n = nbase + n0 + ty + j * 8;
        int k = k0 + tx;
        float v = tl[tx][ty + j * 8];
        __nv_bfloat16 h = __float2bfloat16(v);
        dst[(size_t)n * 4096 + k] = h;
        dst[(size_t)n * 4096 + 2048 + k] = __float2bfloat16(v - __bfloat162float(h));
    }
}

__global__ void tsplit_qkv_kernel(const float* __restrict__ Wq, const float* __restrict__ Wk,
                                  const float* __restrict__ Wv, __nv_bfloat16* __restrict__ dst)
{
    int z = blockIdx.z;
    const float* W = (z == 0) ? Wq : (z == 1) ? Wk : Wv;
    int N     = (z == 0) ? 2048 : 512;
    int nbase = (z == 0) ? 0 : (z == 1) ? 2048 : 2560;
    if ((int)blockIdx.x * 32 >= N) return;
    tsplit_body(W, dst, N, nbase, blockIdx.x, blockIdx.y);
}

__global__ void tsplit_wo_kernel(const float* __restrict__ W, __nv_bfloat16* __restrict__ dst)
{
    tsplit_body(W, dst, 2048, 0, blockIdx.x, blockIdx.y);
}

// ---------------------------------------------------------------------------
// HMMA flash attention, causal, GQA (unchanged from passing round 6).
// ---------------------------------------------------------------------------
#define FA_QHI 0
#define FA_QLO 32768
#define FA_K   65536
#define FA_V   131072
#define FA_PHI 196608
#define FA_PLO 212992
#define FA_SMEM 229376

__global__ __launch_bounds__(256, 1)
void flash_hmma_kernel(const __nv_bfloat16* __restrict__ qh, const __nv_bfloat16* __restrict__ ql,
                       const __nv_bfloat16* __restrict__ kh, const __nv_bfloat16* __restrict__ kl,
                       const __nv_bfloat16* __restrict__ vh, const __nv_bfloat16* __restrict__ vl,
                       __nv_bfloat16* __restrict__ x2)
{
    extern __shared__ __align__(1024) char smem[];
    const uint32_t su = smem_u32_of(smem);
    const int tid  = threadIdx.x;
    const int wid  = tid >> 5;
    const int lane = tid & 31;

    const int qt = (int)gridDim.x - 1 - (int)blockIdx.x;   // long CTAs first
    const int bh = blockIdx.y;
    const int b  = bh >> 4;
    const int h  = bh & 15;
    const int hkv = h >> 2;
    const int q0 = qt * 128;
    const float scale = 0.08838834764831845f;   // 1/sqrt(128)

    const __nv_bfloat16* qhb = qh + (size_t)b * SEQ * QW + h * HDIM;
    const __nv_bfloat16* qlb = ql + (size_t)b * SEQ * QW + h * HDIM;
    const __nv_bfloat16* khb = kh + (size_t)b * SEQ * KW + hkv * HDIM;
    const __nv_bfloat16* klb = kl + (size_t)b * SEQ * KW + hkv * HDIM;
    const __nv_bfloat16* vhb = vh + (size_t)b * SEQ * KW + hkv * HDIM;
    const __nv_bfloat16* vlb = vl + (size_t)b * SEQ * KW + hkv * HDIM;

    for (int i = tid; i < 128 * 16; i += 256) {
        int r = i >> 4, c = i & 15;
        *reinterpret_cast<uint4*>(smem + FA_QHI + SW256(r, c)) =
            *reinterpret_cast<const uint4*>(qhb + (size_t)(q0 + r) * QW + c * 8);
        *reinterpret_cast<uint4*>(smem + FA_QLO + SW256(r, c)) =
            *reinterpret_cast<const uint4*>(qlb + (size_t)(q0 + r) * QW + c * 8);
    }

    const int asel = lane >> 3;
    const int arow = (lane & 7) + ((asel & 1) << 3);
    const int akc  = asel >> 1;
    const int brow = (lane & 7) + ((asel >> 1) << 3);
    const int bkc  = asel & 1;
    const int qrow_s = wid * 16 + arow;

    float o[16][4];
#pragma unroll
    for (int g = 0; g < 16; g++)
#pragma unroll
        for (int e = 0; e < 4; e++) o[g][e] = 0.f;
    float m0 = -1e30f, m1 = -1e30f, l0 = 0.f, l1 = 0.f;

    const int ntiles = 2 * qt + 2;

    auto issueKV = [&](int kt) {
        int k0 = kt * 64;
        uint32_t kbH = su + FA_K + (uint32_t)(kt & 1) * 32768u;
        uint32_t kbL = kbH + 16384u;
        uint32_t vbH = su + FA_V + (uint32_t)(kt & 1) * 32768u;
        uint32_t vbL = vbH + 16384u;
#pragma unroll
        for (int i = 0; i < 4; i++) {
            int id = tid + i * 256;
            int r = id >> 4, c = id & 15;
            size_t go = (size_t)(k0 + r) * KW + c * 8;
            uint32_t so = SW256(r, c);
            cp_async16(kbH + so, khb + go);
            cp_async16(kbL + so, klb + go);
            cp_async16(vbH + so, vhb + go);
            cp_async16(vbL + so, vlb + go);
        }
        cp_commit();
    };

    issueKV(0);

    const int r0g = q0 + wid * 16 + (lane >> 2);
    const int r1g = r0g + 8;
    const int pr0 = wid * 16 + (lane >> 2);
    const int pr1 = pr0 + 8;

    for (int kt = 0; kt < ntiles; ++kt) {
        if (kt + 1 < ntiles) { issueKV(kt + 1); cp_wait1(); }
        else                 { cp_wait0(); }
        __syncthreads();

        uint32_t kbH = su + FA_K + (uint32_t)(kt & 1) * 32768u;
        uint32_t kbL = kbH + 16384u;
        uint32_t vbH = su + FA_V + (uint32_t)(kt & 1) * 32768u;
        uint32_t vbL = vbH + 16384u;

        float s[8][4];
#pragma unroll
        for (int t = 0; t < 8; t++)
#pragma unroll
            for (int e = 0; e < 4; e++) s[t][e] = 0.f;

#pragma unroll
        for (int d = 0; d < 8; ++d) {
            uint32_t ah[4], al[4];
            ldmatrix_x4(ah, su + FA_QHI + SW256(qrow_s, d * 2 + akc));
            ldmatrix_x4(al, su + FA_QLO + SW256(qrow_s, d * 2 + akc));
#pragma unroll
            for (int j = 0; j < 4; ++j) {
                int R = j * 16 + brow;
                uint32_t bhf[4], blf[4];
                ldmatrix_x4(bhf, kbH + SW256(R, d * 2 + bkc));
                ldmatrix_x4(blf, kbL + SW256(R, d * 2 + bkc));
                mma_bf16(s[2 * j],     ah, bhf[0], bhf[1]);
                mma_bf16(s[2 * j + 1], ah, bhf[2], bhf[3]);
                mma_bf16(s[2 * j],     al, bhf[0], bhf[1]);
                mma_bf16(s[2 * j + 1], al, bhf[2], bhf[3]);
                mma_bf16(s[2 * j],     ah, blf[0], blf[1]);
                mma_bf16(s[2 * j + 1], ah, blf[2], blf[3]);
            }
        }

        const int k0 = kt * 64;
        const bool dm = (kt >= 2 * qt);
        float mx0 = -1e30f, mx1 = -1e30f;
#pragma unroll
        for (int t = 0; t < 8; t++) {
            int c0 = k0 + t * 8 + (lane & 3) * 2;
            s[t][0] *= scale; s[t][1] *= scale; s[t][2] *= scale; s[t][3] *= scale;
            if (dm) {
                if (c0     > r0g) s[t][0] = -1e30f;
                if (c0 + 1 > r0g) s[t][1] = -1e30f;
                if (c0     > r1g) s[t][2] = -1e30f;
                if (c0 + 1 > r1g) s[t][3] = -1e30f;
            }
            mx0 = fmaxf(mx0, fmaxf(s[t][0], s[t][1]));
            mx1 = fmaxf(mx1, fmaxf(s[t][2], s[t][3]));
        }
        mx0 = fmaxf(mx0, __shfl_xor_sync(0xffffffffu, mx0, 1));
        mx0 = fmaxf(mx0, __shfl_xor_sync(0xffffffffu, mx0, 2));
        mx1 = fmaxf(mx1, __shfl_xor_sync(0xffffffffu, mx1, 1));
        mx1 = fmaxf(mx1, __shfl_xor_sync(0xffffffffu, mx1, 2));

        float mn0 = fmaxf(m0, mx0), mn1 = fmaxf(m1, mx1);
        float a0 = __expf(m0 - mn0), a1 = __expf(m1 - mn1);
        m0 = mn0; m1 = mn1;

        float rs0 = 0.f, rs1 = 0.f;
#pragma unroll
        for (int t = 0; t < 8; t++) {
            float p0 = __expf(s[t][0] - m0);
            float p1 = __expf(s[t][1] - m0);
            float p2 = __expf(s[t][2] - m1);
            float p3 = __expf(s[t][3] - m1);
            rs0 += p0 + p1; rs1 += p2 + p3;
            __nv_bfloat16 h0 = __float2bfloat16(p0), h1 = __float2bfloat16(p1);
            __nv_bfloat16 h2 = __float2bfloat16(p2), h3 = __float2bfloat16(p3);
            __nv_bfloat162 hp01 = {h0, h1}, hp23 = {h2, h3};
            __nv_bfloat162 lp01 = {__float2bfloat16(p0 - __bfloat162float(h0)),
                                   __float2bfloat16(p1 - __bfloat162float(h1))};
            __nv_bfloat162 lp23 = {__float2bfloat16(p2 - __bfloat162float(h2)),
                                   __float2bfloat16(p3 - __bfloat162float(h3))};
            uint32_t o0 = (uint32_t)(pr0 * 128 + (((t) ^ (pr0 & 7)) << 4) + (lane & 3) * 4);
            uint32_t o1 = (uint32_t)(pr1 * 128 + (((t) ^ (pr1 & 7)) << 4) + (lane & 3) * 4);
            *reinterpret_cast<__nv_bfloat162*>(smem + FA_PHI + o0) = hp01;
            *reinterpret_cast<__nv_bfloat162*>(smem + FA_PHI + o1) = hp23;
            *reinterpret_cast<__nv_bfloat162*>(smem + FA_PLO + o0) = lp01;
            *reinterpret_cast<__nv_bfloat162*>(smem + FA_PLO + o1) = lp23;
        }
        rs0 += __shfl_xor_sync(0xffffffffu, rs0, 1);
        rs0 += __shfl_xor_sync(0xffffffffu, rs0, 2);
        rs1 += __shfl_xor_sync(0xffffffffu, rs1, 1);
        rs1 += __shfl_xor_sync(0xffffffffu, rs1, 2);
        l0 = l0 * a0 + rs0;
        l1 = l1 * a1 + rs1;

#pragma unroll
        for (int g = 0; g < 16; g++) {
            o[g][0] *= a0; o[g][1] *= a0; o[g][2] *= a1; o[g][3] *= a1;
        }
        __syncwarp();

        const int vrow0 = (lane & 7) + ((asel & 1) << 3);
        const int vkc   = asel >> 1;
#pragma unroll
        for (int ks = 0; ks < 4; ++ks) {
            uint32_t ph[4], pl[4];
            ldmatrix_x4(ph, su + FA_PHI + SW128(qrow_s, ks * 2 + akc));
            ldmatrix_x4(pl, su + FA_PLO + SW128(qrow_s, ks * 2 + akc));
            int vr = ks * 16 + vrow0;
#pragma unroll
            for (int g = 0; g < 8; ++g) {
                uint32_t vf[4], vg[4];
                ldmatrix_x4_trans(vf, vbH + SW256(vr, g * 2 + vkc));
                ldmatrix_x4_trans(vg, vbL + SW256(vr, g * 2 + vkc));
                mma_bf16(o[2 * g],     ph, vf[0], vf[1]);
                mma_bf16(o[2 * g + 1], ph, vf[2], vf[3]);
                mma_bf16(o[2 * g],     pl, vf[0], vf[1]);
                mma_bf16(o[2 * g + 1], pl, vf[2], vf[3]);
                mma_bf16(o[2 * g],     ph, vg[0], vg[1]);
                mma_bf16(o[2 * g + 1], ph, vg[2], vg[3]);
            }
        }
        __syncthreads();
    }

    float inv0 = 1.0f / l0, inv1 = 1.0f / l1;
    int row0 = b * SEQ + q0 + wid * 16 + (lane >> 2);
    int row1 = row0 + 8;
#pragma unroll
    for (int g = 0; g < 16; g++) {
        int col = h * HDIM + g * 8 + (lane & 3) * 2;
        float y0 = o[g][0] * inv0, y1 = o[g][1] * inv0;
        float y2 = o[g][2] * inv1, y3 = o[g][3] * inv1;
        split_store2(x2, x2 + 2048, (size_t)row0 * 4096 + col, y0, y1);
        split_store2(x2, x2 + 2048, (size_t)row1 * 4096 + col, y2, y3);
    }
}

// ---------------------------------------------------------------------------
// Launch
// ---------------------------------------------------------------------------
extern "C" void kernel_launch(void* const* d_in, const int* in_sizes, int n_in,
                              void* d_out, int out_size)
{
    const float* x    = (const float*)d_in[0];
    const float* cosp = (const float*)d_in[1];
    const float* sinp = (const float*)d_in[2];
    const float* Wq   = (const float*)d_in[3];
    const float* Wk   = (const float*)d_in[4];
    const float* Wv   = (const float*)d_in[5];
    const float* Wo   = (const float*)d_in[6];
    const float* bo   = (const float*)d_in[7];
    float* out = (float*)d_out;

    __nv_bfloat16 *x2, *wqkv, *wo2, *qh, *ql, *kh, *kl, *vh, *vl;
    cudaGetSymbolAddress((void**)&x2,   g_x2);
    cudaGetSymbolAddress((void**)&wqkv, g_wqkv);
    cudaGetSymbolAddress((void**)&wo2,  g_wo2);
    cudaGetSymbolAddress((void**)&qh,   g_qh);
    cudaGetSymbolAddress((void**)&ql,   g_ql);
    cudaGetSymbolAddress((void**)&kh,   g_kh);
    cudaGetSymbolAddress((void**)&kl,   g_kl);
    cudaGetSymbolAddress((void**)&vh,   g_vh);
    cudaGetSymbolAddress((void**)&vl,   g_vl);

    cudaFuncSetAttribute(hgemm_kernel, cudaFuncAttributeMaxDynamicSharedMemorySize, HG_SMEM);
    cudaFuncSetAttribute(qkv_gemm_kernel, cudaFuncAttributeMaxDynamicSharedMemorySize, HG_SMEM);
    cudaFuncSetAttribute(flash_hmma_kernel, cudaFuncAttributeMaxDynamicSharedMemorySize, FA_SMEM);

    // prep (order chosen so qkv_gemm is our 4th launch -> captured by ncu -s 5)
    tsplit_qkv_kernel<<<dim3(64, 64, 3), dim3(32, 8)>>>(Wq, Wk, Wv, wqkv);
    split2048_kernel<<<MROWS * CDIM / 4 / 256, 256>>>(x, x2);
    tsplit_wo_kernel<<<dim3(64, 64), dim3(32, 8)>>>(Wo, wo2);

    // Fused QKV projection + rmsnorm + rope + splits
    qkv_gemm_kernel<<<dim3(3072 / 128, MROWS / 128), 256, HG_SMEM>>>(
        x2, wqkv, cosp, sinp, qh, ql, kh, kl, vh, vl);

    // HMMA flash attention (writes split output into x2)
    dim3 ga(SEQ / 128, BATCH * NHEAD);
    flash_hmma_kernel<<<ga, 256, FA_SMEM>>>(qh, ql, kh, kl, vh, vl, x2);

    // output projection + bias
    hgemm_kernel<<<dim3(QW / 128, MROWS / 128), 256, HG_SMEM>>>(x2, wo2, out, QW, bo);
}

// round 9
// speedup vs baseline: 1.1061x; 1.1061x over previous
#include <cuda_runtime.h>
#include <cuda_bf16.h>
#include <math.h>
#include <stdint.h>

// Problem constants
#define BATCH 2
#define SEQ   2048
#define CDIM  2048
#define NHEAD 16
#define NKV   4
#define HDIM  128
#define HALF  64
#define MROWS (BATCH*SEQ)          // 4096
#define QW    (NHEAD*HDIM)         // 2048
#define KW    (NKV*HDIM)           // 512

// ---------------------------------------------------------------------------
// Scratch (device globals; no allocations allowed)
// ---------------------------------------------------------------------------
__device__ __nv_bfloat16 g_x2  [4096 * 4096];     // 32 MB (x split; later attn-out split)
__device__ __nv_bfloat16 g_wqkv[3072 * 4096];     // 24 MB packed [Wq|Wk|Wv] transposed split
__device__ __nv_bfloat16 g_wo2 [2048 * 4096];     // 16 MB
__device__ __nv_bfloat16 g_qh[MROWS * QW];        // 16 MB
__device__ __nv_bfloat16 g_ql[MROWS * QW];        // 16 MB
__device__ __nv_bfloat16 g_kh[MROWS * KW];        // 4 MB
__device__ __nv_bfloat16 g_kl[MROWS * KW];        // 4 MB
__device__ __nv_bfloat16 g_vh[MROWS * KW];        // 4 MB
__device__ __nv_bfloat16 g_vl[MROWS * KW];        // 4 MB

// ---------------------------------------------------------------------------
// Baseline-PTX tensor-core helpers
// ---------------------------------------------------------------------------
__device__ __forceinline__ uint32_t smem_u32_of(const void* p) {
    uint32_t a;
    asm("{ .reg .u64 t; cvta.to.shared.u64 t, %1; cvt.u32.u64 %0, t; }" : "=r"(a) : "l"(p));
    return a;
}
__device__ __forceinline__ void cp_async16(uint32_t saddr, const void* gaddr) {
    asm volatile("cp.async.cg.shared.global [%0], [%1], 16;" :: "r"(saddr), "l"(gaddr));
}
__device__ __forceinline__ void cp_commit() {
    asm volatile("cp.async.commit_group;" ::: "memory");
}
__device__ __forceinline__ void cp_wait1() {
    asm volatile("cp.async.wait_group 1;" ::: "memory");
}
__device__ __forceinline__ void cp_wait0() {
    asm volatile("cp.async.wait_group 0;" ::: "memory");
}
__device__ __forceinline__ void ldmatrix_x4(uint32_t* r, uint32_t addr) {
    asm volatile("ldmatrix.sync.aligned.m8n8.x4.shared.b16 {%0,%1,%2,%3}, [%4];"
                 : "=r"(r[0]), "=r"(r[1]), "=r"(r[2]), "=r"(r[3]) : "r"(addr));
}
__device__ __forceinline__ void ldmatrix_x4_trans(uint32_t* r, uint32_t addr) {
    asm volatile("ldmatrix.sync.aligned.m8n8.x4.trans.shared.b16 {%0,%1,%2,%3}, [%4];"
                 : "=r"(r[0]), "=r"(r[1]), "=r"(r[2]), "=r"(r[3]) : "r"(addr));
}
__device__ __forceinline__ void mma_bf16(float* c, const uint32_t* a, uint32_t b0, uint32_t b1) {
    asm volatile(
        "mma.sync.aligned.m16n8k16.row.col.f32.bf16.bf16.f32 "
        "{%0,%1,%2,%3}, {%4,%5,%6,%7}, {%8,%9}, {%0,%1,%2,%3};"
        : "+f"(c[0]), "+f"(c[1]), "+f"(c[2]), "+f"(c[3])
        : "r"(a[0]), "r"(a[1]), "r"(a[2]), "r"(a[3]), "r"(b0), "r"(b1));
}

// swizzled smem offsets (16B chunks, XOR row&7)
#define SW256(r, c) ((uint32_t)((r) * 256 + (((c) ^ ((r) & 7)) << 4)))
#define SW128(r, c) ((uint32_t)((r) * 128 + (((c) ^ ((r) & 7)) << 4)))

// bf16 hi/lo split store of 2 consecutive values
__device__ __forceinline__ void split_store2(__nv_bfloat16* oh, __nv_bfloat16* ol,
                                             size_t idx, float a, float b) {
    __nv_bfloat16 h0 = __float2bfloat16(a), h1 = __float2bfloat16(b);
    __nv_bfloat162 hp = {h0, h1};
    __nv_bfloat162 lp = {__float2bfloat16(a - __bfloat162float(h0)),
                         __float2bfloat16(b - __bfloat162float(h1))};
    *reinterpret_cast<__nv_bfloat162*>(oh + idx) = hp;
    *reinterpret_cast<__nv_bfloat162*>(ol + idx) = lp;
}

// ===========================================================================
// GEMM core: 128x128 CTA tile, BK=64, 3-stage cp.async pipeline.
// A2[M,4096]=[hi|lo] K-major, B2[N,4096]=[hi|lo] K-major; 3 K-segments.
// Register-lean inner loop (B frags first, one A frag at a time) so the
// kernel fits 128 regs -> 2 CTAs/SM.
// ===========================================================================
#define HG_SMEM (3 * 32768)
#define HG_NIT  96

struct GemmFrag { float acc[4][4][4]; };

__device__ __forceinline__ void gemm_mainloop(
    const __nv_bfloat16* __restrict__ A2, const __nv_bfloat16* __restrict__ B2,
    uint32_t su, int m0, int n0, GemmFrag& F)
{
    const int tid  = threadIdx.x;
    const int wid  = tid >> 5;
    const int lane = tid & 31;
    const int ld = 4096;

    uint32_t smoff[4];
    const __nv_bfloat16 *gA[4], *gB[4];
#pragma unroll
    for (int i = 0; i < 4; i++) {
        int id = tid + i * 256;
        int r = id >> 3, c = id & 7;
        smoff[i] = (uint32_t)(r * 128 + ((c ^ (r & 7)) << 4));
        gA[i] = A2 + (size_t)(m0 + r) * ld + c * 8;
        gB[i] = B2 + (size_t)(n0 + r) * ld + c * 8;
    }

    const int mwarp = (wid >> 2) * 64;
    const int nwarp = (wid & 3) * 32;

    const int asel = lane >> 3;
    const int arow = (lane & 7) + ((asel & 1) << 3);
    const int akc  = asel >> 1;
    const int brow = (lane & 7) + ((asel >> 1) << 3);
    const int bkc  = asel & 1;

#pragma unroll
    for (int mf = 0; mf < 4; mf++)
#pragma unroll
        for (int nf = 0; nf < 4; nf++)
#pragma unroll
            for (int e = 0; e < 4; e++) F.acc[mf][nf][e] = 0.f;

    auto issue = [&](int it, int stage) {
        int seg = it >> 5;
        int t   = it & 31;
        int aoff = t * 64 + (seg == 1 ? 2048 : 0);
        int boff = t * 64 + (seg == 2 ? 2048 : 0);
        uint32_t ab = su + (uint32_t)stage * 32768u;
        uint32_t bb = ab + 16384u;
#pragma unroll
        for (int i = 0; i < 4; i++) {
            cp_async16(ab + smoff[i], gA[i] + aoff);
            cp_async16(bb + smoff[i], gB[i] + boff);
        }
        cp_commit();
    };

    issue(0, 0);
    issue(1, 1);

    int sCur = 0, sNxt = 2;
    for (int it = 0; it < HG_NIT; ++it) {
        if (it + 1 < HG_NIT) cp_wait1();
        else                 cp_wait0();
        __syncthreads();
        if (it + 2 < HG_NIT) issue(it + 2, sNxt);

        uint32_t abase = su + (uint32_t)sCur * 32768u;
        uint32_t bbase = abase + 16384u;

#pragma unroll
        for (int ks = 0; ks < 4; ++ks) {
            uint32_t br[2][4];
#pragma unroll
            for (int bh = 0; bh < 2; bh++) {
                int R = nwarp + bh * 16 + brow;
                int ch = ks * 2 + bkc;
                ldmatrix_x4(br[bh], bbase + R * 128 + (uint32_t)((ch ^ (R & 7)) << 4));
            }
#pragma unroll
            for (int mf = 0; mf < 4; mf++) {
                uint32_t af[4];
                int R = mwarp + mf * 16 + arow;
                int ch = ks * 2 + akc;
                ldmatrix_x4(af, abase + R * 128 + (uint32_t)((ch ^ (R & 7)) << 4));
                mma_bf16(F.acc[mf][0], af, br[0][0], br[0][1]);
                mma_bf16(F.acc[mf][1], af, br[0][2], br[0][3]);
                mma_bf16(F.acc[mf][2], af, br[1][0], br[1][1]);
                mma_bf16(F.acc[mf][3], af, br[1][2], br[1][3]);
            }
        }
        sCur = (sCur == 2) ? 0 : sCur + 1;
        sNxt = (sNxt == 2) ? 0 : sNxt + 1;
    }
}

// ---------------------------------------------------------------------------
// Generic GEMM with fp32 output + optional bias (used for Wo).
// ---------------------------------------------------------------------------
__global__ __launch_bounds__(256, 2)
void hgemm_kernel(const __nv_bfloat16* __restrict__ A2, const __nv_bfloat16* __restrict__ B2,
                  float* __restrict__ C, int N, const float* __restrict__ bias)
{
    extern __shared__ __align__(1024) char smem[];
    const uint32_t su = smem_u32_of(smem);
    const int tid  = threadIdx.x;
    const int wid  = tid >> 5;
    const int lane = tid & 31;
    const int m0 = blockIdx.y * 128;
    const int n0 = blockIdx.x * 128;

    GemmFrag F;
    gemm_mainloop(A2, B2, su, m0, n0, F);

    const int mwarp = (wid >> 2) * 64;
    const int nwarp = (wid & 3) * 32;
    const int mrow = lane >> 2;
    const int ncol = (lane & 3) * 2;
#pragma unroll
    for (int mf = 0; mf < 4; mf++) {
#pragma unroll
        for (int nf = 0; nf < 4; nf++) {
            int gm = m0 + mwarp + mf * 16 + mrow;
            int gn = n0 + nwarp + nf * 8 + ncol;
            float b0 = 0.f, b1 = 0.f;
            if (bias != nullptr) { b0 = bias[gn]; b1 = bias[gn + 1]; }
            float2 lo = make_float2(F.acc[mf][nf][0] + b0, F.acc[mf][nf][1] + b1);
            float2 hi = make_float2(F.acc[mf][nf][2] + b0, F.acc[mf][nf][3] + b1);
            *reinterpret_cast<float2*>(C + (size_t)gm * N + gn)       = lo;
            *reinterpret_cast<float2*>(C + (size_t)(gm + 8) * N + gn) = hi;
        }
    }
}

// ---------------------------------------------------------------------------
// Fused QKV GEMM + per-head RMSNorm + RoPE + bf16 split epilogue.
//   cols [0,2048)    -> q heads: rmsnorm+rope -> qh/ql
//   cols [2048,2560) -> k heads: rmsnorm+rope -> kh/kl
//   cols [2560,3072) -> v: plain bf16 hi/lo split -> vh/vl
// ---------------------------------------------------------------------------
__global__ __launch_bounds__(256, 2)
void qkv_gemm_kernel(const __nv_bfloat16* __restrict__ A2, const __nv_bfloat16* __restrict__ B2,
                     const float* __restrict__ cosp, const float* __restrict__ sinp,
                     __nv_bfloat16* __restrict__ qh, __nv_bfloat16* __restrict__ ql,
                     __nv_bfloat16* __restrict__ kh, __nv_bfloat16* __restrict__ kl,
                     __nv_bfloat16* __restrict__ vh, __nv_bfloat16* __restrict__ vl)
{
    extern __shared__ __align__(1024) char smem[];
    const uint32_t su = smem_u32_of(smem);
    const int tid  = threadIdx.x;
    const int wid  = tid >> 5;
    const int lane = tid & 31;
    const int m0 = blockIdx.y * 128;
    const int n0 = blockIdx.x * 128;

    GemmFrag F;
    gemm_mainloop(A2, B2, su, m0, n0, F);

    const int mwarp = (wid >> 2) * 64;
    const int nwarp = (wid & 3) * 32;
    const int mrow = lane >> 2;
    const int ncol = (lane & 3) * 2;

    if (n0 >= 2560) {
        // V region: plain bf16 hi/lo split
#pragma unroll
        for (int mf = 0; mf < 4; mf++)
#pragma unroll
            for (int nf = 0; nf < 4; nf++) {
                int gm = m0 + mwarp + mf * 16 + mrow;
                int gn = n0 - 2560 + nwarp + nf * 8 + ncol;
                split_store2(vh, vl, (size_t)gm * 512 + gn,
                             F.acc[mf][nf][0], F.acc[mf][nf][1]);
                split_store2(vh, vl, (size_t)(gm + 8) * 512 + gn,
                             F.acc[mf][nf][2], F.acc[mf][nf][3]);
            }
        return;
    }

    // ---- Q/K region: RMSNorm + RoPE + split, all in-CTA ----
    __syncthreads();   // pipeline smem no longer needed; safe to reuse
    const int NP = 132;
    float* ntile = reinterpret_cast<float*>(smem);     // [128][132] fp32
    float* ssqp  = ntile + 128 * NP;                   // [4][128]
    float* rmsv  = ssqp + 512;                         // [128]

    // stage fp32 values + per-warp row ssq partials
#pragma unroll
    for (int mf = 0; mf < 4; mf++) {
        int lr0 = mwarp + mf * 16 + mrow;
        int lr1 = lr0 + 8;
        float p0 = 0.f, p1 = 0.f;
#pragma unroll
        for (int nf = 0; nf < 4; nf++) {
            int cc = nwarp + nf * 8 + ncol;
            float a0 = F.acc[mf][nf][0], a1 = F.acc[mf][nf][1];
            float a2 = F.acc[mf][nf][2], a3 = F.acc[mf][nf][3];
            ntile[lr0 * NP + cc]     = a0;
            ntile[lr0 * NP + cc + 1] = a1;
            ntile[lr1 * NP + cc]     = a2;
            ntile[lr1 * NP + cc + 1] = a3;
            p0 += a0 * a0 + a1 * a1;
            p1 += a2 * a2 + a3 * a3;
        }
        p0 += __shfl_xor_sync(0xffffffffu, p0, 1);
        p0 += __shfl_xor_sync(0xffffffffu, p0, 2);
        p1 += __shfl_xor_sync(0xffffffffu, p1, 1);
        p1 += __shfl_xor_sync(0xffffffffu, p1, 2);
        if ((lane & 3) == 0) {
            ssqp[(wid & 3) * 128 + lr0] = p0;
            ssqp[(wid & 3) * 128 + lr1] = p1;
        }
    }
    __syncthreads();
    if (tid < 128) {
        float s = ssqp[tid] + ssqp[128 + tid] + ssqp[256 + tid] + ssqp[384 + tid];
        rmsv[tid] = rsqrtf(s * (1.0f / 128.0f) + 1.1920929e-7f);
    }
    __syncthreads();

    // RoPE + split: 2 threads per row, 32 dims each half
    {
        int r = tid >> 1;
        int dbase = (tid & 1) * 32;
        int gm = m0 + r;
        int t  = gm & (SEQ - 1);
        float rm = rmsv[r];
        const bool isq = (n0 < 2048);
        __nv_bfloat16* oh = isq ? qh : kh;
        __nv_bfloat16* ol = isq ? ql : kl;
        size_t stride = isq ? 2048 : 512;
        int colbase = isq ? n0 : (n0 - 2048);
        size_t rowoff = (size_t)gm * stride + colbase;
        const float* crow = cosp + t * HALF;
        const float* srow = sinp + t * HALF;
        const float* nrow = ntile + r * NP;
#pragma unroll 4
        for (int j = 0; j < 32; j += 2) {
            int d = dbase + j;
            float v0a = nrow[d]      * rm, v1a = nrow[d + 64] * rm;
            float v0b = nrow[d + 1]  * rm, v1b = nrow[d + 65] * rm;
            float ca = crow[d],     sa = srow[d];
            float cb = crow[d + 1], sb = srow[d + 1];
            split_store2(oh, ol, rowoff + d,      v0a * ca - v1a * sa, v0b * cb - v1b * sb);
            split_store2(oh, ol, rowoff + 64 + d, v0a * sa + v1a * ca, v0b * sb + v1b * cb);
        }
    }
}

// ---------------------------------------------------------------------------
// fp32 -> (hi, lo) bf16 split. src [M, 2048] -> dst [M, 4096] ([hi|lo]).
// ---------------------------------------------------------------------------
__global__ void split2048_kernel(const float* __restrict__ src, __nv_bfloat16* __restrict__ dst)
{
    int i = blockIdx.x * 256 + threadIdx.x;
    float4 v = reinterpret_cast<const float4*>(src)[i];
    int e = i * 4;
    int m = e >> 11;
    int k = e & 2047;
    __nv_bfloat16* d = dst + (size_t)m * 4096 + k;
    __nv_bfloat16 h0 = __float2bfloat16(v.x), h1 = __float2bfloat16(v.y);
    __nv_bfloat16 h2 = __float2bfloat16(v.z), h3 = __float2bfloat16(v.w);
    d[0] = h0; d[1] = h1; d[2] = h2; d[3] = h3;
    d[2048] = __float2bfloat16(v.x - __bfloat162float(h0));
    d[2049] = __float2bfloat16(v.y - __bfloat162float(h1));
    d[2050] = __float2bfloat16(v.z - __bfloat162float(h2));
    d[2051] = __float2bfloat16(v.w - __bfloat162float(h3));
}

// ---------------------------------------------------------------------------
// Transposed split of W [2048, N] into dst columns [nbase, nbase+N).
// ---------------------------------------------------------------------------
__device__ __forceinline__ void tsplit_body(const float* __restrict__ W,
                                            __nv_bfloat16* __restrict__ dst,
                                            int N, int nbase, int bx, int by)
{
    __shared__ float tl[32][33];
    int tx = threadIdx.x, ty = threadIdx.y;
    int n0 = bx * 32, k0 = by * 32;
#pragma unroll
    for (int j = 0; j < 4; j++)
        tl[ty + j * 8][tx] = W[(size_t)(k0 + ty + j * 8) * N + n0 + tx];
    __syncthreads();
#pragma unroll
    for (int j = 0; j < 4; j++) {
        int n = nbase + n0 + ty + j * 8;
        int k = k0 + tx;
        float v = tl[tx][ty + j * 8];
        __nv_bfloat16 h = __float2bfloat16(v);
        dst[(size_t)n * 4096 + k] = h;
        dst[(size_t)n * 4096 + 2048 + k] = __float2bfloat16(v - __bfloat162float(h));
    }
}

__global__ void tsplit_qkv_kernel(const float* __restrict__ Wq, const float* __restrict__ Wk,
                                  const float* __restrict__ Wv, __nv_bfloat16* __restrict__ dst)
{
    int z = blockIdx.z;
    const float* W = (z == 0) ? Wq : (z == 1) ? Wk : Wv;
    int N     = (z == 0) ? 2048 : 512;
    int nbase = (z == 0) ? 0 : (z == 1) ? 2048 : 2560;
    if ((int)blockIdx.x * 32 >= N) return;
    tsplit_body(W, dst, N, nbase, blockIdx.x, blockIdx.y);
}

__global__ void tsplit_wo_kernel(const float* __restrict__ W, __nv_bfloat16* __restrict__ dst)
{
    tsplit_body(W, dst, 2048, 0, blockIdx.x, blockIdx.y);
}

// ---------------------------------------------------------------------------
// HMMA flash attention, causal, GQA (unchanged).
// ---------------------------------------------------------------------------
#define FA_QHI 0
#define FA_QLO 32768
#define FA_K   65536
#define FA_V   131072
#define FA_PHI 196608
#define FA_PLO 212992
#define FA_SMEM 229376

__global__ __launch_bounds__(256, 1)
void flash_hmma_kernel(const __nv_bfloat16* __restrict__ qh, const __nv_bfloat16* __restrict__ ql,
                       const __nv_bfloat16* __restrict__ kh, const __nv_bfloat16* __restrict__ kl,
                       const __nv_bfloat16* __restrict__ vh, const __nv_bfloat16* __restrict__ vl,
                       __nv_bfloat16* __restrict__ x2)
{
    extern __shared__ __align__(1024) char smem[];
    const uint32_t su = smem_u32_of(smem);
    const int tid  = threadIdx.x;
    const int wid  = tid >> 5;
    const int lane = tid & 31;

    const int qt = (int)gridDim.x - 1 - (int)blockIdx.x;   // long CTAs first
    const int bh = blockIdx.y;
    const int b  = bh >> 4;
    const int h  = bh & 15;
    const int hkv = h >> 2;
    const int q0 = qt * 128;
    const float scale = 0.08838834764831845f;   // 1/sqrt(128)

    const __nv_bfloat16* qhb = qh + (size_t)b * SEQ * QW + h * HDIM;
    const __nv_bfloat16* qlb = ql + (size_t)b * SEQ * QW + h * HDIM;
    const __nv_bfloat16* khb = kh + (size_t)b * SEQ * KW + hkv * HDIM;
    const __nv_bfloat16* klb = kl + (size_t)b * SEQ * KW + hkv * HDIM;
    const __nv_bfloat16* vhb = vh + (size_t)b * SEQ * KW + hkv * HDIM;
    const __nv_bfloat16* vlb = vl + (size_t)b * SEQ * KW + hkv * HDIM;

    for (int i = tid; i < 128 * 16; i += 256) {
        int r = i >> 4, c = i & 15;
        *reinterpret_cast<uint4*>(smem + FA_QHI + SW256(r, c)) =
            *reinterpret_cast<const uint4*>(qhb + (size_t)(q0 + r) * QW + c * 8);
        *reinterpret_cast<uint4*>(smem + FA_QLO + SW256(r, c)) =
            *reinterpret_cast<const uint4*>(qlb + (size_t)(q0 + r) * QW + c * 8);
    }

    const int asel = lane >> 3;
    const int arow = (lane & 7) + ((asel & 1) << 3);
    const int akc  = asel >> 1;
    const int brow = (lane & 7) + ((asel >> 1) << 3);
    const int bkc  = asel & 1;
    const int qrow_s = wid * 16 + arow;

    float o[16][4];
#pragma unroll
    for (int g = 0; g < 16; g++)
#pragma unroll
        for (int e = 0; e < 4; e++) o[g][e] = 0.f;
    float m0 = -1e30f, m1 = -1e30f, l0 = 0.f, l1 = 0.f;

    const int ntiles = 2 * qt + 2;

    auto issueKV = [&](int kt) {
        int k0 = kt * 64;
        uint32_t kbH = su + FA_K + (uint32_t)(kt & 1) * 32768u;
        uint32_t kbL = kbH + 16384u;
        uint32_t vbH = su + FA_V + (uint32_t)(kt & 1) * 32768u;
        uint32_t vbL = vbH + 16384u;
#pragma unroll
        for (int i = 0; i < 4; i++) {
            int id = tid + i * 256;
            int r = id >> 4, c = id & 15;
            size_t go = (size_t)(k0 + r) * KW + c * 8;
            uint32_t so = SW256(r, c);
            cp_async16(kbH + so, khb + go);
            cp_async16(kbL + so, klb + go);
            cp_async16(vbH + so, vhb + go);
            cp_async16(vbL + so, vlb + go);
        }
        cp_commit();
    };

    issueKV(0);

    const int r0g = q0 + wid * 16 + (lane >> 2);
    const int r1g = r0g + 8;
    const int pr0 = wid * 16 + (lane >> 2);
    const int pr1 = pr0 + 8;

    for (int kt = 0; kt < ntiles; ++kt) {
        if (kt + 1 < ntiles) { issueKV(kt + 1); cp_wait1(); }
        else                 { cp_wait0(); }
        __syncthreads();

        uint32_t kbH = su + FA_K + (uint32_t)(kt & 1) * 32768u;
        uint32_t kbL = kbH + 16384u;
        uint32_t vbH = su + FA_V + (uint32_t)(kt & 1) * 32768u;
        uint32_t vbL = vbH + 16384u;

        float s[8][4];
#pragma unroll
        for (int t = 0; t < 8; t++)
#pragma unroll
            for (int e = 0; e < 4; e++) s[t][e] = 0.f;

#pragma unroll
        for (int d = 0; d < 8; ++d) {
            uint32_t ah[4], al[4];
            ldmatrix_x4(ah, su + FA_QHI + SW256(qrow_s, d * 2 + akc));
            ldmatrix_x4(al, su + FA_QLO + SW256(qrow_s, d * 2 + akc));
#pragma unroll
            for (int j = 0; j < 4; ++j) {
                int R = j * 16 + brow;
                uint32_t bhf[4], blf[4];
                ldmatrix_x4(bhf, kbH + SW256(R, d * 2 + bkc));
                ldmatrix_x4(blf, kbL + SW256(R, d * 2 + bkc));
                mma_bf16(s[2 * j],     ah, bhf[0], bhf[1]);
                mma_bf16(s[2 * j + 1], ah, bhf[2], bhf[3]);
                mma_bf16(s[2 * j],     al, bhf[0], bhf[1]);
                mma_bf16(s[2 * j + 1], al, bhf[2], bhf[3]);
                mma_bf16(s[2 * j],     ah, blf[0], blf[1]);
                mma_bf16(s[2 * j + 1], ah, blf[2], blf[3]);
            }
        }

        const int k0 = kt * 64;
        const bool dm = (kt >= 2 * qt);
        float mx0 = -1e30f, mx1 = -1e30f;
#pragma unroll
        for (int t = 0; t < 8; t++) {
            int c0 = k0 + t * 8 + (lane & 3) * 2;
            s[t][0] *= scale; s[t][1] *= scale; s[t][2] *= scale; s[t][3] *= scale;
            if (dm) {
                if (c0     > r0g) s[t][0] = -1e30f;
                if (c0 + 1 > r0g) s[t][1] = -1e30f;
                if (c0     > r1g) s[t][2] = -1e30f;
                if (c0 + 1 > r1g) s[t][3] = -1e30f;
            }
            mx0 = fmaxf(mx0, fmaxf(s[t][0], s[t][1]));
            mx1 = fmaxf(mx1, fmaxf(s[t][2], s[t][3]));
        }
        mx0 = fmaxf(mx0, __shfl_xor_sync(0xffffffffu, mx0, 1));
        mx0 = fmaxf(mx0, __shfl_xor_sync(0xffffffffu, mx0, 2));
        mx1 = fmaxf(mx1, __shfl_xor_sync(0xffffffffu, mx1, 1));
        mx1 = fmaxf(mx1, __shfl_xor_sync(0xffffffffu, mx1, 2));

        float mn0 = fmaxf(m0, mx0), mn1 = fmaxf(m1, mx1);
        float a0 = __expf(m0 - mn0), a1 = __expf(m1 - mn1);
        m0 = mn0; m1 = mn1;

        float rs0 = 0.f, rs1 = 0.f;
#pragma unroll
        for (int t = 0; t < 8; t++) {
            float p0 = __expf(s[t][0] - m0);
            float p1 = __expf(s[t][1] - m0);
            float p2 = __expf(s[t][2] - m1);
            float p3 = __expf(s[t][3] - m1);
            rs0 += p0 + p1; rs1 += p2 + p3;
            __nv_bfloat16 h0 = __float2bfloat16(p0), h1 = __float2bfloat16(p1);
            __nv_bfloat16 h2 = __float2bfloat16(p2), h3 = __float2bfloat16(p3);
            __nv_bfloat162 hp01 = {h0, h1}, hp23 = {h2, h3};
            __nv_bfloat162 lp01 = {__float2bfloat16(p0 - __bfloat162float(h0)),
                                   __float2bfloat16(p1 - __bfloat162float(h1))};
            __nv_bfloat162 lp23 = {__float2bfloat16(p2 - __bfloat162float(h2)),
                                   __float2bfloat16(p3 - __bfloat162float(h3))};
            uint32_t o0 = (uint32_t)(pr0 * 128 + (((t) ^ (pr0 & 7)) << 4) + (lane & 3) * 4);
            uint32_t o1 = (uint32_t)(pr1 * 128 + (((t) ^ (pr1 & 7)) << 4) + (lane & 3) * 4);
            *reinterpret_cast<__nv_bfloat162*>(smem + FA_PHI + o0) = hp01;
            *reinterpret_cast<__nv_bfloat162*>(smem + FA_PHI + o1) = hp23;
            *reinterpret_cast<__nv_bfloat162*>(smem + FA_PLO + o0) = lp01;
            *reinterpret_cast<__nv_bfloat162*>(smem + FA_PLO + o1) = lp23;
        }
        rs0 += __shfl_xor_sync(0xffffffffu, rs0, 1);
        rs0 += __shfl_xor_sync(0xffffffffu, rs0, 2);
        rs1 += __shfl_xor_sync(0xffffffffu, rs1, 1);
        rs1 += __shfl_xor_sync(0xffffffffu, rs1, 2);
        l0 = l0 * a0 + rs0;
        l1 = l1 * a1 + rs1;

#pragma unroll
        for (int g = 0; g < 16; g++) {
            o[g][0] *= a0; o[g][1] *= a0; o[g][2] *= a1; o[g][3] *= a1;
        }
        __syncwarp();

        const int vrow0 = (lane & 7) + ((asel & 1) << 3);
        const int vkc   = asel >> 1;
#pragma unroll
        for (int ks = 0; ks < 4; ++ks) {
            uint32_t ph[4], pl[4];
            ldmatrix_x4(ph, su + FA_PHI + SW128(qrow_s, ks * 2 + akc));
            ldmatrix_x4(pl, su + FA_PLO + SW128(qrow_s, ks * 2 + akc));
            int vr = ks * 16 + vrow0;
#pragma unroll
            for (int g = 0; g < 8; ++g) {
                uint32_t vf[4], vg[4];
                ldmatrix_x4_trans(vf, vbH + SW256(vr, g * 2 + vkc));
                ldmatrix_x4_trans(vg, vbL + SW256(vr, g * 2 + vkc));
                mma_bf16(o[2 * g],     ph, vf[0], vf[1]);
                mma_bf16(o[2 * g + 1], ph, vf[2], vf[3]);
                mma_bf16(o[2 * g],     pl, vf[0], vf[1]);
                mma_bf16(o[2 * g + 1], pl, vf[2], vf[3]);
                mma_bf16(o[2 * g],     ph, vg[0], vg[1]);
                mma_bf16(o[2 * g + 1], ph, vg[2], vg[3]);
            }
        }
        __syncthreads();
    }

    float inv0 = 1.0f / l0, inv1 = 1.0f / l1;
    int row0 = b * SEQ + q0 + wid * 16 + (lane >> 2);
    int row1 = row0 + 8;
#pragma unroll
    for (int g = 0; g < 16; g++) {
        int col = h * HDIM + g * 8 + (lane & 3) * 2;
        float y0 = o[g][0] * inv0, y1 = o[g][1] * inv0;
        float y2 = o[g][2] * inv1, y3 = o[g][3] * inv1;
        split_store2(x2, x2 + 2048, (size_t)row0 * 4096 + col, y0, y1);
        split_store2(x2, x2 + 2048, (size_t)row1 * 4096 + col, y2, y3);
    }
}

// ---------------------------------------------------------------------------
// Launch
// ---------------------------------------------------------------------------
extern "C" void kernel_launch(void* const* d_in, const int* in_sizes, int n_in,
                              void* d_out, int out_size)
{
    const float* x    = (const float*)d_in[0];
    const float* cosp = (const float*)d_in[1];
    const float* sinp = (const float*)d_in[2];
    const float* Wq   = (const float*)d_in[3];
    const float* Wk   = (const float*)d_in[4];
    const float* Wv   = (const float*)d_in[5];
    const float* Wo   = (const float*)d_in[6];
    const float* bo   = (const float*)d_in[7];
    float* out = (float*)d_out;

    __nv_bfloat16 *x2, *wqkv, *wo2, *qh, *ql, *kh, *kl, *vh, *vl;
    cudaGetSymbolAddress((void**)&x2,   g_x2);
    cudaGetSymbolAddress((void**)&wqkv, g_wqkv);
    cudaGetSymbolAddress((void**)&wo2,  g_wo2);
    cudaGetSymbolAddress((void**)&qh,   g_qh);
    cudaGetSymbolAddress((void**)&ql,   g_ql);
    cudaGetSymbolAddress((void**)&kh,   g_kh);
    cudaGetSymbolAddress((void**)&kl,   g_kl);
    cudaGetSymbolAddress((void**)&vh,   g_vh);
    cudaGetSymbolAddress((void**)&vl,   g_vl);

    cudaFuncSetAttribute(hgemm_kernel, cudaFuncAttributeMaxDynamicSharedMemorySize, HG_SMEM);
    cudaFuncSetAttribute(qkv_gemm_kernel, cudaFuncAttributeMaxDynamicSharedMemorySize, HG_SMEM);
    cudaFuncSetAttribute(flash_hmma_kernel, cudaFuncAttributeMaxDynamicSharedMemorySize, FA_SMEM);

    // prep (order chosen so qkv_gemm is our 4th launch -> captured by ncu -s 5)
    tsplit_qkv_kernel<<<dim3(64, 64, 3), dim3(32, 8)>>>(Wq, Wk, Wv, wqkv);
    split2048_kernel<<<MROWS * CDIM / 4 / 256, 256>>>(x, x2);
    tsplit_wo_kernel<<<dim3(64, 64), dim3(32, 8)>>>(Wo, wo2);

    // Fused QKV projection + rmsnorm + rope + splits
    qkv_gemm_kernel<<<dim3(3072 / 128, MROWS / 128), 256, HG_SMEM>>>(
        x2, wqkv, cosp, sinp, qh, ql, kh, kl, vh, vl);

    // HMMA flash attention (writes split output into x2)
    dim3 ga(SEQ / 128, BATCH * NHEAD);
    flash_hmma_kernel<<<ga, 256, FA_SMEM>>>(qh, ql, kh, kl, vh, vl, x2);

    // output projection + bias
    hgemm_kernel<<<dim3(QW / 128, MROWS / 128), 256, HG_SMEM>>>(x2, wo2, out, QW, bo);
}

// round 10
// speedup vs baseline: 1.3739x; 1.2421x over previous
#include <cuda_runtime.h>
#include <cuda_bf16.h>
#include <cuda_fp16.h>
#include <math.h>
#include <stdint.h>

// Problem constants
#define BATCH 2
#define SEQ   2048
#define CDIM  2048
#define NHEAD 16
#define NKV   4
#define HDIM  128
#define HALF  64
#define MROWS (BATCH*SEQ)          // 4096
#define QW    (NHEAD*HDIM)         // 2048
#define KW    (NKV*HDIM)           // 512

// ---------------------------------------------------------------------------
// Scratch (device globals; no allocations allowed)
// ---------------------------------------------------------------------------
__device__ __half g_x2  [4096 * 4096];            // 32 MB fp16 [hi|lo] (x; later attn-out)
__device__ __half g_wqkv[3072 * 2048];            // 12 MB packed [Wq|Wk|Wv]^T fp16
__device__ __half g_wo2 [2048 * 2048];            // 8 MB Wo^T fp16
__device__ __nv_bfloat16 g_qh[MROWS * QW];        // 16 MB
__device__ __nv_bfloat16 g_ql[MROWS * QW];        // 16 MB
__device__ __nv_bfloat16 g_kh[MROWS * KW];        // 4 MB
__device__ __nv_bfloat16 g_kl[MROWS * KW];        // 4 MB
__device__ __nv_bfloat16 g_vh[MROWS * KW];        // 4 MB
__device__ __nv_bfloat16 g_vl[MROWS * KW];        // 4 MB

// ---------------------------------------------------------------------------
// Baseline-PTX tensor-core helpers
// ---------------------------------------------------------------------------
__device__ __forceinline__ uint32_t smem_u32_of(const void* p) {
    uint32_t a;
    asm("{ .reg .u64 t; cvta.to.shared.u64 t, %1; cvt.u32.u64 %0, t; }" : "=r"(a) : "l"(p));
    return a;
}
__device__ __forceinline__ void cp_async16(uint32_t saddr, const void* gaddr) {
    asm volatile("cp.async.cg.shared.global [%0], [%1], 16;" :: "r"(saddr), "l"(gaddr));
}
__device__ __forceinline__ void cp_commit() {
    asm volatile("cp.async.commit_group;" ::: "memory");
}
__device__ __forceinline__ void cp_wait1() {
    asm volatile("cp.async.wait_group 1;" ::: "memory");
}
__device__ __forceinline__ void cp_wait0() {
    asm volatile("cp.async.wait_group 0;" ::: "memory");
}
__device__ __forceinline__ void ldmatrix_x4(uint32_t* r, uint32_t addr) {
    asm volatile("ldmatrix.sync.aligned.m8n8.x4.shared.b16 {%0,%1,%2,%3}, [%4];"
                 : "=r"(r[0]), "=r"(r[1]), "=r"(r[2]), "=r"(r[3]) : "r"(addr));
}
__device__ __forceinline__ void ldmatrix_x4_trans(uint32_t* r, uint32_t addr) {
    asm volatile("ldmatrix.sync.aligned.m8n8.x4.trans.shared.b16 {%0,%1,%2,%3}, [%4];"
                 : "=r"(r[0]), "=r"(r[1]), "=r"(r[2]), "=r"(r[3]) : "r"(addr));
}
__device__ __forceinline__ void mma_bf16(float* c, const uint32_t* a, uint32_t b0, uint32_t b1) {
    asm volatile(
        "mma.sync.aligned.m16n8k16.row.col.f32.bf16.bf16.f32 "
        "{%0,%1,%2,%3}, {%4,%5,%6,%7}, {%8,%9}, {%0,%1,%2,%3};"
        : "+f"(c[0]), "+f"(c[1]), "+f"(c[2]), "+f"(c[3])
        : "r"(a[0]), "r"(a[1]), "r"(a[2]), "r"(a[3]), "r"(b0), "r"(b1));
}
__device__ __forceinline__ void mma_fp16(float* c, const uint32_t* a, uint32_t b0, uint32_t b1) {
    asm volatile(
        "mma.sync.aligned.m16n8k16.row.col.f32.f16.f16.f32 "
        "{%0,%1,%2,%3}, {%4,%5,%6,%7}, {%8,%9}, {%0,%1,%2,%3};"
        : "+f"(c[0]), "+f"(c[1]), "+f"(c[2]), "+f"(c[3])
        : "r"(a[0]), "r"(a[1]), "r"(a[2]), "r"(a[3]), "r"(b0), "r"(b1));
}

// swizzled smem offsets (16B chunks, XOR row&7)
#define SW256(r, c) ((uint32_t)((r) * 256 + (((c) ^ ((r) & 7)) << 4)))
#define SW128(r, c) ((uint32_t)((r) * 128 + (((c) ^ ((r) & 7)) << 4)))

// bf16 hi/lo split store of 2 consecutive values
__device__ __forceinline__ void split_store2(__nv_bfloat16* oh, __nv_bfloat16* ol,
                                             size_t idx, float a, float b) {
    __nv_bfloat16 h0 = __float2bfloat16(a), h1 = __float2bfloat16(b);
    __nv_bfloat162 hp = {h0, h1};
    __nv_bfloat162 lp = {__float2bfloat16(a - __bfloat162float(h0)),
                         __float2bfloat16(b - __bfloat162float(h1))};
    *reinterpret_cast<__nv_bfloat162*>(oh + idx) = hp;
    *reinterpret_cast<__nv_bfloat162*>(ol + idx) = lp;
}
// fp16 hi/lo split store of 2 consecutive values
__device__ __forceinline__ void split_store2h(__half* oh, __half* ol,
                                              size_t idx, float a, float b) {
    __half h0 = __float2half(a), h1 = __float2half(b);
    __half2 hp = {h0, h1};
    __half2 lp = {__float2half(a - __half2float(h0)),
                  __float2half(b - __half2float(h1))};
    *reinterpret_cast<__half2*>(oh + idx) = hp;
    *reinterpret_cast<__half2*>(ol + idx) = lp;
}

// ===========================================================================
// fp16 GEMM core: 128x128 CTA tile, BK=64, 3-stage cp.async pipeline.
// A2[M,4096] fp16 [hi|lo] K-major, B[N,2048] fp16 K-major.
// C = Ah*B + Al*B  (2 K-segments, NIT=64).
// ===========================================================================
#define HG_SMEM (3 * 32768)
#define HG_NIT  64

struct GemmFrag { float acc[4][4][4]; };

__device__ __forceinline__ void gemm_mainloop(
    const __half* __restrict__ A2, const __half* __restrict__ B,
    uint32_t su, int m0, int n0, GemmFrag& F)
{
    const int tid  = threadIdx.x;
    const int wid  = tid >> 5;
    const int lane = tid & 31;

    uint32_t smoff[4];
    const __half *gA[4], *gB[4];
#pragma unroll
    for (int i = 0; i < 4; i++) {
        int id = tid + i * 256;
        int r = id >> 3, c = id & 7;
        smoff[i] = (uint32_t)(r * 128 + ((c ^ (r & 7)) << 4));
        gA[i] = A2 + (size_t)(m0 + r) * 4096 + c * 8;
        gB[i] = B  + (size_t)(n0 + r) * 2048 + c * 8;
    }

    const int mwarp = (wid >> 2) * 64;
    const int nwarp = (wid & 3) * 32;

    const int asel = lane >> 3;
    const int arow = (lane & 7) + ((asel & 1) << 3);
    const int akc  = asel >> 1;
    const int brow = (lane & 7) + ((asel >> 1) << 3);
    const int bkc  = asel & 1;

#pragma unroll
    for (int mf = 0; mf < 4; mf++)
#pragma unroll
        for (int nf = 0; nf < 4; nf++)
#pragma unroll
            for (int e = 0; e < 4; e++) F.acc[mf][nf][e] = 0.f;

    auto issue = [&](int it, int stage) {
        int seg = it >> 5;
        int t   = it & 31;
        int aoff = t * 64 + (seg == 1 ? 2048 : 0);
        int boff = t * 64;
        uint32_t ab = su + (uint32_t)stage * 32768u;
        uint32_t bb = ab + 16384u;
#pragma unroll
        for (int i = 0; i < 4; i++) {
            cp_async16(ab + smoff[i], gA[i] + aoff);
            cp_async16(bb + smoff[i], gB[i] + boff);
        }
        cp_commit();
    };

    issue(0, 0);
    issue(1, 1);

    int sCur = 0, sNxt = 2;
    for (int it = 0; it < HG_NIT; ++it) {
        if (it + 1 < HG_NIT) cp_wait1();
        else                 cp_wait0();
        __syncthreads();
        if (it + 2 < HG_NIT) issue(it + 2, sNxt);

        uint32_t abase = su + (uint32_t)sCur * 32768u;
        uint32_t bbase = abase + 16384u;

#pragma unroll
        for (int ks = 0; ks < 4; ++ks) {
            uint32_t br[2][4];
#pragma unroll
            for (int bh = 0; bh < 2; bh++) {
                int R = nwarp + bh * 16 + brow;
                int ch = ks * 2 + bkc;
                ldmatrix_x4(br[bh], bbase + R * 128 + (uint32_t)((ch ^ (R & 7)) << 4));
            }
#pragma unroll
            for (int mf = 0; mf < 4; mf++) {
                uint32_t af[4];
                int R = mwarp + mf * 16 + arow;
                int ch = ks * 2 + akc;
                ldmatrix_x4(af, abase + R * 128 + (uint32_t)((ch ^ (R & 7)) << 4));
                mma_fp16(F.acc[mf][0], af, br[0][0], br[0][1]);
                mma_fp16(F.acc[mf][1], af, br[0][2], br[0][3]);
                mma_fp16(F.acc[mf][2], af, br[1][0], br[1][1]);
                mma_fp16(F.acc[mf][3], af, br[1][2], br[1][3]);
            }
        }
        sCur = (sCur == 2) ? 0 : sCur + 1;
        sNxt = (sNxt == 2) ? 0 : sNxt + 1;
    }
}

// ---------------------------------------------------------------------------
// Generic GEMM with fp32 output + optional bias (used for Wo).
// ---------------------------------------------------------------------------
__global__ __launch_bounds__(256, 2)
void hgemm_kernel(const __half* __restrict__ A2, const __half* __restrict__ B,
                  float* __restrict__ C, int N, const float* __restrict__ bias)
{
    extern __shared__ __align__(1024) char smem[];
    const uint32_t su = smem_u32_of(smem);
    const int tid  = threadIdx.x;
    const int wid  = tid >> 5;
    const int lane = tid & 31;
    const int m0 = blockIdx.y * 128;
    const int n0 = blockIdx.x * 128;

    GemmFrag F;
    gemm_mainloop(A2, B, su, m0, n0, F);

    const int mwarp = (wid >> 2) * 64;
    const int nwarp = (wid & 3) * 32;
    const int mrow = lane >> 2;
    const int ncol = (lane & 3) * 2;
#pragma unroll
    for (int mf = 0; mf < 4; mf++) {
#pragma unroll
        for (int nf = 0; nf < 4; nf++) {
            int gm = m0 + mwarp + mf * 16 + mrow;
            int gn = n0 + nwarp + nf * 8 + ncol;
            float b0 = 0.f, b1 = 0.f;
            if (bias != nullptr) { b0 = bias[gn]; b1 = bias[gn + 1]; }
            float2 lo = make_float2(F.acc[mf][nf][0] + b0, F.acc[mf][nf][1] + b1);
            float2 hi = make_float2(F.acc[mf][nf][2] + b0, F.acc[mf][nf][3] + b1);
            *reinterpret_cast<float2*>(C + (size_t)gm * N + gn)       = lo;
            *reinterpret_cast<float2*>(C + (size_t)(gm + 8) * N + gn) = hi;
        }
    }
}

// ---------------------------------------------------------------------------
// Fused QKV GEMM + per-head RMSNorm + RoPE + bf16 split epilogue.
//   cols [0,2048)    -> q heads: rmsnorm+rope -> qh/ql (bf16)
//   cols [2048,2560) -> k heads: rmsnorm+rope -> kh/kl (bf16)
//   cols [2560,3072) -> v: plain bf16 hi/lo split -> vh/vl
// ---------------------------------------------------------------------------
__global__ __launch_bounds__(256, 2)
void qkv_gemm_kernel(const __half* __restrict__ A2, const __half* __restrict__ B,
                     const float* __restrict__ cosp, const float* __restrict__ sinp,
                     __nv_bfloat16* __restrict__ qh, __nv_bfloat16* __restrict__ ql,
                     __nv_bfloat16* __restrict__ kh, __nv_bfloat16* __restrict__ kl,
                     __nv_bfloat16* __restrict__ vh, __nv_bfloat16* __restrict__ vl)
{
    extern __shared__ __align__(1024) char smem[];
    const uint32_t su = smem_u32_of(smem);
    const int tid  = threadIdx.x;
    const int wid  = tid >> 5;
    const int lane = tid & 31;
    const int m0 = blockIdx.y * 128;
    const int n0 = blockIdx.x * 128;

    GemmFrag F;
    gemm_mainloop(A2, B, su, m0, n0, F);

    const int mwarp = (wid >> 2) * 64;
    const int nwarp = (wid & 3) * 32;
    const int mrow = lane >> 2;
    const int ncol = (lane & 3) * 2;

    if (n0 >= 2560) {
        // V region: plain bf16 hi/lo split
#pragma unroll
        for (int mf = 0; mf < 4; mf++)
#pragma unroll
            for (int nf = 0; nf < 4; nf++) {
                int gm = m0 + mwarp + mf * 16 + mrow;
                int gn = n0 - 2560 + nwarp + nf * 8 + ncol;
                split_store2(vh, vl, (size_t)gm * 512 + gn,
                             F.acc[mf][nf][0], F.acc[mf][nf][1]);
                split_store2(vh, vl, (size_t)(gm + 8) * 512 + gn,
                             F.acc[mf][nf][2], F.acc[mf][nf][3]);
            }
        return;
    }

    // ---- Q/K region: RMSNorm + RoPE + split, all in-CTA ----
    __syncthreads();   // pipeline smem no longer needed; safe to reuse
    const int NP = 132;
    float* ntile = reinterpret_cast<float*>(smem);     // [128][132] fp32
    float* ssqp  = ntile + 128 * NP;                   // [4][128]
    float* rmsv  = ssqp + 512;                         // [128]

#pragma unroll
    for (int mf = 0; mf < 4; mf++) {
        int lr0 = mwarp + mf * 16 + mrow;
        int lr1 = lr0 + 8;
        float p0 = 0.f, p1 = 0.f;
#pragma unroll
        for (int nf = 0; nf < 4; nf++) {
            int cc = nwarp + nf * 8 + ncol;
            float a0 = F.acc[mf][nf][0], a1 = F.acc[mf][nf][1];
            float a2 = F.acc[mf][nf][2], a3 = F.acc[mf][nf][3];
            ntile[lr0 * NP + cc]     = a0;
            ntile[lr0 * NP + cc + 1] = a1;
            ntile[lr1 * NP + cc]     = a2;
            ntile[lr1 * NP + cc + 1] = a3;
            p0 += a0 * a0 + a1 * a1;
            p1 += a2 * a2 + a3 * a3;
        }
        p0 += __shfl_xor_sync(0xffffffffu, p0, 1);
        p0 += __shfl_xor_sync(0xffffffffu, p0, 2);
        p1 += __shfl_xor_sync(0xffffffffu, p1, 1);
        p1 += __shfl_xor_sync(0xffffffffu, p1, 2);
        if ((lane & 3) == 0) {
            ssqp[(wid & 3) * 128 + lr0] = p0;
            ssqp[(wid & 3) * 128 + lr1] = p1;
        }
    }
    __syncthreads();
    if (tid < 128) {
        float s = ssqp[tid] + ssqp[128 + tid] + ssqp[256 + tid] + ssqp[384 + tid];
        rmsv[tid] = rsqrtf(s * (1.0f / 128.0f) + 1.1920929e-7f);
    }
    __syncthreads();

    // RoPE + split: 2 threads per row, 32 dims each half
    {
        int r = tid >> 1;
        int dbase = (tid & 1) * 32;
        int gm = m0 + r;
        int t  = gm & (SEQ - 1);
        float rm = rmsv[r];
        const bool isq = (n0 < 2048);
        __nv_bfloat16* oh = isq ? qh : kh;
        __nv_bfloat16* ol = isq ? ql : kl;
        size_t stride = isq ? 2048 : 512;
        int colbase = isq ? n0 : (n0 - 2048);
        size_t rowoff = (size_t)gm * stride + colbase;
        const float* crow = cosp + t * HALF;
        const float* srow = sinp + t * HALF;
        const float* nrow = ntile + r * NP;
#pragma unroll 4
        for (int j = 0; j < 32; j += 2) {
            int d = dbase + j;
            float v0a = nrow[d]      * rm, v1a = nrow[d + 64] * rm;
            float v0b = nrow[d + 1]  * rm, v1b = nrow[d + 65] * rm;
            float ca = crow[d],     sa = srow[d];
            float cb = crow[d + 1], sb = srow[d + 1];
            split_store2(oh, ol, rowoff + d,      v0a * ca - v1a * sa, v0b * cb - v1b * sb);
            split_store2(oh, ol, rowoff + 64 + d, v0a * sa + v1a * ca, v0b * sb + v1b * cb);
        }
    }
}

// ---------------------------------------------------------------------------
// fp32 -> (hi, lo) fp16 split. src [M, 2048] -> dst [M, 4096] ([hi|lo]).
// ---------------------------------------------------------------------------
__global__ void split2048_kernel(const float* __restrict__ src, __half* __restrict__ dst)
{
    int i = blockIdx.x * 256 + threadIdx.x;
    float4 v = reinterpret_cast<const float4*>(src)[i];
    int e = i * 4;
    int m = e >> 11;
    int k = e & 2047;
    __half* d = dst + (size_t)m * 4096 + k;
    __half h0 = __float2half(v.x), h1 = __float2half(v.y);
    __half h2 = __float2half(v.z), h3 = __float2half(v.w);
    d[0] = h0; d[1] = h1; d[2] = h2; d[3] = h3;
    d[2048] = __float2half(v.x - __half2float(h0));
    d[2049] = __float2half(v.y - __half2float(h1));
    d[2050] = __float2half(v.z - __half2float(h2));
    d[2051] = __float2half(v.w - __half2float(h3));
}

// ---------------------------------------------------------------------------
// Transposed fp16 convert of W [2048, N] into dst columns [nbase, nbase+N),
// K-major [n][2048].
// ---------------------------------------------------------------------------
__device__ __forceinline__ void tconv_body(const float* __restrict__ W,
                                           __half* __restrict__ dst,
                                           int N, int nbase, int bx, int by)
{
    __shared__ float tl[32][33];
    int tx = threadIdx.x, ty = threadIdx.y;
    int n0 = bx * 32, k0 = by * 32;
#pragma unroll
    for (int j = 0; j < 4; j++)
        tl[ty + j * 8][tx] = W[(size_t)(k0 + ty + j * 8) * N + n0 + tx];
    __syncthreads();
#pragma unroll
    for (int j = 0; j < 4; j++) {
        int n = nbase + n0 + ty + j * 8;
        int k = k0 + tx;
        dst[(size_t)n * 2048 + k] = __float2half(tl[tx][ty + j * 8]);
    }
}

__global__ void tconv_qkv_kernel(const float* __restrict__ Wq, const float* __restrict__ Wk,
                                 const float* __restrict__ Wv, __half* __restrict__ dst)
{
    int z = blockIdx.z;
    const float* W = (z == 0) ? Wq : (z == 1) ? Wk : Wv;
    int N     = (z == 0) ? 2048 : 512;
    int nbase = (z == 0) ? 0 : (z == 1) ? 2048 : 2560;
    if ((int)blockIdx.x * 32 >= N) return;
    tconv_body(W, dst, N, nbase, blockIdx.x, blockIdx.y);
}

__global__ void tconv_wo_kernel(const float* __restrict__ W, __half* __restrict__ dst)
{
    tconv_body(W, dst, 2048, 0, blockIdx.x, blockIdx.y);
}

// ---------------------------------------------------------------------------
// HMMA flash attention, causal, GQA (bf16 3-term; unchanged except fp16
// output split into x2).
// ---------------------------------------------------------------------------
#define FA_QHI 0
#define FA_QLO 32768
#define FA_K   65536
#define FA_V   131072
#define FA_PHI 196608
#define FA_PLO 212992
#define FA_SMEM 229376

__global__ __launch_bounds__(256, 1)
void flash_hmma_kernel(const __nv_bfloat16* __restrict__ qh, const __nv_bfloat16* __restrict__ ql,
                       const __nv_bfloat16* __restrict__ kh, const __nv_bfloat16* __restrict__ kl,
                       const __nv_bfloat16* __restrict__ vh, const __nv_bfloat16* __restrict__ vl,
                       __half* __restrict__ x2)
{
    extern __shared__ __align__(1024) char smem[];
    const uint32_t su = smem_u32_of(smem);
    const int tid  = threadIdx.x;
    const int wid  = tid >> 5;
    const int lane = tid & 31;

    const int qt = (int)gridDim.x - 1 - (int)blockIdx.x;   // long CTAs first
    const int bh = blockIdx.y;
    const int b  = bh >> 4;
    const int h  = bh & 15;
    const int hkv = h >> 2;
    const int q0 = qt * 128;
    const float scale = 0.08838834764831845f;   // 1/sqrt(128)

    const __nv_bfloat16* qhb = qh + (size_t)b * SEQ * QW + h * HDIM;
    const __nv_bfloat16* qlb = ql + (size_t)b * SEQ * QW + h * HDIM;
    const __nv_bfloat16* khb = kh + (size_t)b * SEQ * KW + hkv * HDIM;
    const __nv_bfloat16* klb = kl + (size_t)b * SEQ * KW + hkv * HDIM;
    const __nv_bfloat16* vhb = vh + (size_t)b * SEQ * KW + hkv * HDIM;
    const __nv_bfloat16* vlb = vl + (size_t)b * SEQ * KW + hkv * HDIM;

    for (int i = tid; i < 128 * 16; i += 256) {
        int r = i >> 4, c = i & 15;
        *reinterpret_cast<uint4*>(smem + FA_QHI + SW256(r, c)) =
            *reinterpret_cast<const uint4*>(qhb + (size_t)(q0 + r) * QW + c * 8);
        *reinterpret_cast<uint4*>(smem + FA_QLO + SW256(r, c)) =
            *reinterpret_cast<const uint4*>(qlb + (size_t)(q0 + r) * QW + c * 8);
    }

    const int asel = lane >> 3;
    const int arow = (lane & 7) + ((asel & 1) << 3);
    const int akc  = asel >> 1;
    const int brow = (lane & 7) + ((asel >> 1) << 3);
    const int bkc  = asel & 1;
    const int qrow_s = wid * 16 + arow;

    float o[16][4];
#pragma unroll
    for (int g = 0; g < 16; g++)
#pragma unroll
        for (int e = 0; e < 4; e++) o[g][e] = 0.f;
    float m0 = -1e30f, m1 = -1e30f, l0 = 0.f, l1 = 0.f;

    const int ntiles = 2 * qt + 2;

    auto issueKV = [&](int kt) {
        int k0 = kt * 64;
        uint32_t kbH = su + FA_K + (uint32_t)(kt & 1) * 32768u;
        uint32_t kbL = kbH + 16384u;
        uint32_t vbH = su + FA_V + (uint32_t)(kt & 1) * 32768u;
        uint32_t vbL = vbH + 16384u;
#pragma unroll
        for (int i = 0; i < 4; i++) {
            int id = tid + i * 256;
            int r = id >> 4, c = id & 15;
            size_t go = (size_t)(k0 + r) * KW + c * 8;
            uint32_t so = SW256(r, c);
            cp_async16(kbH + so, khb + go);
            cp_async16(kbL + so, klb + go);
            cp_async16(vbH + so, vhb + go);
            cp_async16(vbL + so, vlb + go);
        }
        cp_commit();
    };

    issueKV(0);

    const int r0g = q0 + wid * 16 + (lane >> 2);
    const int r1g = r0g + 8;
    const int pr0 = wid * 16 + (lane >> 2);
    const int pr1 = pr0 + 8;

    for (int kt = 0; kt < ntiles; ++kt) {
        if (kt + 1 < ntiles) { issueKV(kt + 1); cp_wait1(); }
        else                 { cp_wait0(); }
        __syncthreads();

        uint32_t kbH = su + FA_K + (uint32_t)(kt & 1) * 32768u;
        uint32_t kbL = kbH + 16384u;
        uint32_t vbH = su + FA_V + (uint32_t)(kt & 1) * 32768u;
        uint32_t vbL = vbH + 16384u;

        float s[8][4];
#pragma unroll
        for (int t = 0; t < 8; t++)
#pragma unroll
            for (int e = 0; e < 4; e++) s[t][e] = 0.f;

#pragma unroll
        for (int d = 0; d < 8; ++d) {
            uint32_t ah[4], al[4];
            ldmatrix_x4(ah, su + FA_QHI + SW256(qrow_s, d * 2 + akc));
            ldmatrix_x4(al, su + FA_QLO + SW256(qrow_s, d * 2 + akc));
#pragma unroll
            for (int j = 0; j < 4; ++j) {
                int R = j * 16 + brow;
                uint32_t bhf[4], blf[4];
                ldmatrix_x4(bhf, kbH + SW256(R, d * 2 + bkc));
                ldmatrix_x4(blf, kbL + SW256(R, d * 2 + bkc));
                mma_bf16(s[2 * j],     ah, bhf[0], bhf[1]);
                mma_bf16(s[2 * j + 1], ah, bhf[2], bhf[3]);
                mma_bf16(s[2 * j],     al, bhf[0], bhf[1]);
                mma_bf16(s[2 * j + 1], al, bhf[2], bhf[3]);
                mma_bf16(s[2 * j],     ah, blf[0], blf[1]);
                mma_bf16(s[2 * j + 1], ah, blf[2], blf[3]);
            }
        }

        const int k0 = kt * 64;
        const bool dm = (kt >= 2 * qt);
        float mx0 = -1e30f, mx1 = -1e30f;
#pragma unroll
        for (int t = 0; t < 8; t++) {
            int c0 = k0 + t * 8 + (lane & 3) * 2;
            s[t][0] *= scale; s[t][1] *= scale; s[t][2] *= scale; s[t][3] *= scale;
            if (dm) {
                if (c0     > r0g) s[t][0] = -1e30f;
                if (c0 + 1 > r0g) s[t][1] = -1e30f;
                if (c0     > r1g) s[t][2] = -1e30f;
                if (c0 + 1 > r1g) s[t][3] = -1e30f;
            }
            mx0 = fmaxf(mx0, fmaxf(s[t][0], s[t][1]));
            mx1 = fmaxf(mx1, fmaxf(s[t][2], s[t][3]));
        }
        mx0 = fmaxf(mx0, __shfl_xor_sync(0xffffffffu, mx0, 1));
        mx0 = fmaxf(mx0, __shfl_xor_sync(0xffffffffu, mx0, 2));
        mx1 = fmaxf(mx1, __shfl_xor_sync(0xffffffffu, mx1, 1));
        mx1 = fmaxf(mx1, __shfl_xor_sync(0xffffffffu, mx1, 2));

        float mn0 = fmaxf(m0, mx0), mn1 = fmaxf(m1, mx1);
        float a0 = __expf(m0 - mn0), a1 = __expf(m1 - mn1);
        m0 = mn0; m1 = mn1;

        float rs0 = 0.f, rs1 = 0.f;
#pragma unroll
        for (int t = 0; t < 8; t++) {
            float p0 = __expf(s[t][0] - m0);
            float p1 = __expf(s[t][1] - m0);
            float p2 = __expf(s[t][2] - m1);
            float p3 = __expf(s[t][3] - m1);
            rs0 += p0 + p1; rs1 += p2 + p3;
            __nv_bfloat16 h0 = __float2bfloat16(p0), h1 = __float2bfloat16(p1);
            __nv_bfloat16 h2 = __float2bfloat16(p2), h3 = __float2bfloat16(p3);
            __nv_bfloat162 hp01 = {h0, h1}, hp23 = {h2, h3};
            __nv_bfloat162 lp01 = {__float2bfloat16(p0 - __bfloat162float(h0)),
                                   __float2bfloat16(p1 - __bfloat162float(h1))};
            __nv_bfloat162 lp23 = {__float2bfloat16(p2 - __bfloat162float(h2)),
                                   __float2bfloat16(p3 - __bfloat162float(h3))};
            uint32_t o0 = (uint32_t)(pr0 * 128 + (((t) ^ (pr0 & 7)) << 4) + (lane & 3) * 4);
            uint32_t o1 = (uint32_t)(pr1 * 128 + (((t) ^ (pr1 & 7)) << 4) + (lane & 3) * 4);
            *reinterpret_cast<__nv_bfloat162*>(smem + FA_PHI + o0) = hp01;
            *reinterpret_cast<__nv_bfloat162*>(smem + FA_PHI + o1) = hp23;
            *reinterpret_cast<__nv_bfloat162*>(smem + FA_PLO + o0) = lp01;
            *reinterpret_cast<__nv_bfloat162*>(smem + FA_PLO + o1) = lp23;
        }
        rs0 += __shfl_xor_sync(0xffffffffu, rs0, 1);
        rs0 += __shfl_xor_sync(0xffffffffu, rs0, 2);
        rs1 += __shfl_xor_sync(0xffffffffu, rs1, 1);
        rs1 += __shfl_xor_sync(0xffffffffu, rs1, 2);
        l0 = l0 * a0 + rs0;
        l1 = l1 * a1 + rs1;

#pragma unroll
        for (int g = 0; g < 16; g++) {
            o[g][0] *= a0; o[g][1] *= a0; o[g][2] *= a1; o[g][3] *= a1;
        }
        __syncwarp();

        const int vrow0 = (lane & 7) + ((asel & 1) << 3);
        const int vkc   = asel >> 1;
#pragma unroll
        for (int ks = 0; ks < 4; ++ks) {
            uint32_t ph[4], pl[4];
            ldmatrix_x4(ph, su + FA_PHI + SW128(qrow_s, ks * 2 + akc));
            ldmatrix_x4(pl, su + FA_PLO + SW128(qrow_s, ks * 2 + akc));
            int vr = ks * 16 + vrow0;
#pragma unroll
            for (int g = 0; g < 8; ++g) {
                uint32_t vf[4], vg[4];
                ldmatrix_x4_trans(vf, vbH + SW256(vr, g * 2 + vkc));
                ldmatrix_x4_trans(vg, vbL + SW256(vr, g * 2 + vkc));
                mma_bf16(o[2 * g],     ph, vf[0], vf[1]);
                mma_bf16(o[2 * g + 1], ph, vf[2], vf[3]);
                mma_bf16(o[2 * g],     pl, vf[0], vf[1]);
                mma_bf16(o[2 * g + 1], pl, vf[2], vf[3]);
                mma_bf16(o[2 * g],     ph, vg[0], vg[1]);
                mma_bf16(o[2 * g + 1], ph, vg[2], vg[3]);
            }
        }
        __syncthreads();
    }

    float inv0 = 1.0f / l0, inv1 = 1.0f / l1;
    int row0 = b * SEQ + q0 + wid * 16 + (lane >> 2);
    int row1 = row0 + 8;
#pragma unroll
    for (int g = 0; g < 16; g++) {
        int col = h * HDIM + g * 8 + (lane & 3) * 2;
        float y0 = o[g][0] * inv0, y1 = o[g][1] * inv0;
        float y2 = o[g][2] * inv1, y3 = o[g][3] * inv1;
        split_store2h(x2, x2 + 2048, (size_t)row0 * 4096 + col, y0, y1);
        split_store2h(x2, x2 + 2048, (size_t)row1 * 4096 + col, y2, y3);
    }
}

// ---------------------------------------------------------------------------
// Launch
// ---------------------------------------------------------------------------
extern "C" void kernel_launch(void* const* d_in, const int* in_sizes, int n_in,
                              void* d_out, int out_size)
{
    const float* x    = (const float*)d_in[0];
    const float* cosp = (const float*)d_in[1];
    const float* sinp = (const float*)d_in[2];
    const float* Wq   = (const float*)d_in[3];
    const float* Wk   = (const float*)d_in[4];
    const float* Wv   = (const float*)d_in[5];
    const float* Wo   = (const float*)d_in[6];
    const float* bo   = (const float*)d_in[7];
    float* out = (float*)d_out;

    __half *x2, *wqkv, *wo2;
    __nv_bfloat16 *qh, *ql, *kh, *kl, *vh, *vl;
    cudaGetSymbolAddress((void**)&x2,   g_x2);
    cudaGetSymbolAddress((void**)&wqkv, g_wqkv);
    cudaGetSymbolAddress((void**)&wo2,  g_wo2);
    cudaGetSymbolAddress((void**)&qh,   g_qh);
    cudaGetSymbolAddress((void**)&ql,   g_ql);
    cudaGetSymbolAddress((void**)&kh,   g_kh);
    cudaGetSymbolAddress((void**)&kl,   g_kl);
    cudaGetSymbolAddress((void**)&vh,   g_vh);
    cudaGetSymbolAddress((void**)&vl,   g_vl);

    cudaFuncSetAttribute(hgemm_kernel, cudaFuncAttributeMaxDynamicSharedMemorySize, HG_SMEM);
    cudaFuncSetAttribute(qkv_gemm_kernel, cudaFuncAttributeMaxDynamicSharedMemorySize, HG_SMEM);
    cudaFuncSetAttribute(flash_hmma_kernel, cudaFuncAttributeMaxDynamicSharedMemorySize, FA_SMEM);

    // prep (order keeps qkv_gemm as our 4th launch for ncu -s 5)
    tconv_qkv_kernel<<<dim3(64, 64, 3), dim3(32, 8)>>>(Wq, Wk, Wv, wqkv);
    split2048_kernel<<<MROWS * CDIM / 4 / 256, 256>>>(x, x2);
    tconv_wo_kernel<<<dim3(64, 64), dim3(32, 8)>>>(Wo, wo2);

    // Fused QKV projection + rmsnorm + rope + splits (fp16 2-segment GEMM)
    qkv_gemm_kernel<<<dim3(3072 / 128, MROWS / 128), 256, HG_SMEM>>>(
        x2, wqkv, cosp, sinp, qh, ql, kh, kl, vh, vl);

    // HMMA flash attention (bf16 3-term; writes fp16 split output into x2)
    dim3 ga(SEQ / 128, BATCH * NHEAD);
    flash_hmma_kernel<<<ga, 256, FA_SMEM>>>(qh, ql, kh, kl, vh, vl, x2);

    // output projection + bias (fp16 2-segment GEMM)
    hgemm_kernel<<<dim3(QW / 128, MROWS / 128), 256, HG_SMEM>>>(x2, wo2, out, QW, bo);
}

// round 11
// speedup vs baseline: 1.5425x; 1.1228x over previous
#include <cuda_runtime.h>
#include <cuda_bf16.h>
#include <cuda_fp16.h>
#include <math.h>
#include <stdint.h>

// Problem constants
#define BATCH 2
#define SEQ   2048
#define CDIM  2048
#define NHEAD 16
#define NKV   4
#define HDIM  128
#define HALF  64
#define MROWS (BATCH*SEQ)          // 4096
#define QW    (NHEAD*HDIM)         // 2048
#define KW    (NKV*HDIM)           // 512

// ---------------------------------------------------------------------------
// Scratch (device globals; no allocations allowed)
// ---------------------------------------------------------------------------
__device__ __half g_x2  [4096 * 4096];            // 32 MB fp16 [hi|lo] (x; later attn-out)
__device__ __half g_wqkv[3072 * 2048];            // 12 MB packed [Wq|Wk|Wv]^T fp16
__device__ __half g_wo2 [2048 * 2048];            // 8 MB Wo^T fp16
__device__ __half g_qh[MROWS * QW];               // 16 MB fp16 q hi
__device__ __half g_ql[MROWS * QW];               // 16 MB fp16 q lo
__device__ __half g_kh[MROWS * KW];               // 4 MB fp16 k (single)
__device__ __half g_vh[MROWS * KW];               // 4 MB fp16 v (single)

// ---------------------------------------------------------------------------
// Baseline-PTX tensor-core helpers
// ---------------------------------------------------------------------------
__device__ __forceinline__ uint32_t smem_u32_of(const void* p) {
    uint32_t a;
    asm("{ .reg .u64 t; cvta.to.shared.u64 t, %1; cvt.u32.u64 %0, t; }" : "=r"(a) : "l"(p));
    return a;
}
__device__ __forceinline__ void cp_async16(uint32_t saddr, const void* gaddr) {
    asm volatile("cp.async.cg.shared.global [%0], [%1], 16;" :: "r"(saddr), "l"(gaddr));
}
__device__ __forceinline__ void cp_commit() {
    asm volatile("cp.async.commit_group;" ::: "memory");
}
__device__ __forceinline__ void cp_wait1() {
    asm volatile("cp.async.wait_group 1;" ::: "memory");
}
__device__ __forceinline__ void cp_wait0() {
    asm volatile("cp.async.wait_group 0;" ::: "memory");
}
__device__ __forceinline__ void ldmatrix_x4(uint32_t* r, uint32_t addr) {
    asm volatile("ldmatrix.sync.aligned.m8n8.x4.shared.b16 {%0,%1,%2,%3}, [%4];"
                 : "=r"(r[0]), "=r"(r[1]), "=r"(r[2]), "=r"(r[3]) : "r"(addr));
}
__device__ __forceinline__ void ldmatrix_x4_trans(uint32_t* r, uint32_t addr) {
    asm volatile("ldmatrix.sync.aligned.m8n8.x4.trans.shared.b16 {%0,%1,%2,%3}, [%4];"
                 : "=r"(r[0]), "=r"(r[1]), "=r"(r[2]), "=r"(r[3]) : "r"(addr));
}
__device__ __forceinline__ void mma_fp16(float* c, const uint32_t* a, uint32_t b0, uint32_t b1) {
    asm volatile(
        "mma.sync.aligned.m16n8k16.row.col.f32.f16.f16.f32 "
        "{%0,%1,%2,%3}, {%4,%5,%6,%7}, {%8,%9}, {%0,%1,%2,%3};"
        : "+f"(c[0]), "+f"(c[1]), "+f"(c[2]), "+f"(c[3])
        : "r"(a[0]), "r"(a[1]), "r"(a[2]), "r"(a[3]), "r"(b0), "r"(b1));
}

// swizzled smem offsets (16B chunks, XOR row&7)
#define SW256(r, c) ((uint32_t)((r) * 256 + (((c) ^ ((r) & 7)) << 4)))
#define SW128(r, c) ((uint32_t)((r) * 128 + (((c) ^ ((r) & 7)) << 4)))

// fp16 hi/lo split store of 2 consecutive values
__device__ __forceinline__ void split_store2h(__half* oh, __half* ol,
                                              size_t idx, float a, float b) {
    __half h0 = __float2half(a), h1 = __float2half(b);
    __half2 hp = {h0, h1};
    __half2 lp = {__float2half(a - __half2float(h0)),
                  __float2half(b - __half2float(h1))};
    *reinterpret_cast<__half2*>(oh + idx) = hp;
    *reinterpret_cast<__half2*>(ol + idx) = lp;
}
__device__ __forceinline__ void store2h(__half* o, size_t idx, float a, float b) {
    __half2 hp = {__float2half(a), __float2half(b)};
    *reinterpret_cast<__half2*>(o + idx) = hp;
}

// ===========================================================================
// fp16 GEMM core: 128x128 CTA tile, BK=64, 3-stage cp.async pipeline.
// A2[M,4096] fp16 [hi|lo] K-major, B[N,2048] fp16 K-major.
// C = Ah*B + Al*B  (2 K-segments, NIT=64).
// ===========================================================================
#define HG_SMEM (3 * 32768)
#define HG_NIT  64

struct GemmFrag { float acc[4][4][4]; };

__device__ __forceinline__ void gemm_mainloop(
    const __half* __restrict__ A2, const __half* __restrict__ B,
    uint32_t su, int m0, int n0, GemmFrag& F)
{
    const int tid  = threadIdx.x;
    const int wid  = tid >> 5;
    const int lane = tid & 31;

    uint32_t smoff[4];
    const __half *gA[4], *gB[4];
#pragma unroll
    for (int i = 0; i < 4; i++) {
        int id = tid + i * 256;
        int r = id >> 3, c = id & 7;
        smoff[i] = (uint32_t)(r * 128 + ((c ^ (r & 7)) << 4));
        gA[i] = A2 + (size_t)(m0 + r) * 4096 + c * 8;
        gB[i] = B  + (size_t)(n0 + r) * 2048 + c * 8;
    }

    const int mwarp = (wid >> 2) * 64;
    const int nwarp = (wid & 3) * 32;

    const int asel = lane >> 3;
    const int arow = (lane & 7) + ((asel & 1) << 3);
    const int akc  = asel >> 1;
    const int brow = (lane & 7) + ((asel >> 1) << 3);
    const int bkc  = asel & 1;

#pragma unroll
    for (int mf = 0; mf < 4; mf++)
#pragma unroll
        for (int nf = 0; nf < 4; nf++)
#pragma unroll
            for (int e = 0; e < 4; e++) F.acc[mf][nf][e] = 0.f;

    auto issue = [&](int it, int stage) {
        int seg = it >> 5;
        int t   = it & 31;
        int aoff = t * 64 + (seg == 1 ? 2048 : 0);
        int boff = t * 64;
        uint32_t ab = su + (uint32_t)stage * 32768u;
        uint32_t bb = ab + 16384u;
#pragma unroll
        for (int i = 0; i < 4; i++) {
            cp_async16(ab + smoff[i], gA[i] + aoff);
            cp_async16(bb + smoff[i], gB[i] + boff);
        }
        cp_commit();
    };

    issue(0, 0);
    issue(1, 1);

    int sCur = 0, sNxt = 2;
    for (int it = 0; it < HG_NIT; ++it) {
        if (it + 1 < HG_NIT) cp_wait1();
        else                 cp_wait0();
        __syncthreads();
        if (it + 2 < HG_NIT) issue(it + 2, sNxt);

        uint32_t abase = su + (uint32_t)sCur * 32768u;
        uint32_t bbase = abase + 16384u;

#pragma unroll
        for (int ks = 0; ks < 4; ++ks) {
            uint32_t br[2][4];
#pragma unroll
            for (int bh = 0; bh < 2; bh++) {
                int R = nwarp + bh * 16 + brow;
                int ch = ks * 2 + bkc;
                ldmatrix_x4(br[bh], bbase + R * 128 + (uint32_t)((ch ^ (R & 7)) << 4));
            }
#pragma unroll
            for (int mf = 0; mf < 4; mf++) {
                uint32_t af[4];
                int R = mwarp + mf * 16 + arow;
                int ch = ks * 2 + akc;
                ldmatrix_x4(af, abase + R * 128 + (uint32_t)((ch ^ (R & 7)) << 4));
                mma_fp16(F.acc[mf][0], af, br[0][0], br[0][1]);
                mma_fp16(F.acc[mf][1], af, br[0][2], br[0][3]);
                mma_fp16(F.acc[mf][2], af, br[1][0], br[1][1]);
                mma_fp16(F.acc[mf][3], af, br[1][2], br[1][3]);
            }
        }
        sCur = (sCur == 2) ? 0 : sCur + 1;
        sNxt = (sNxt == 2) ? 0 : sNxt + 1;
    }
}

// ---------------------------------------------------------------------------
// Generic GEMM with fp32 output + optional bias (used for Wo).
// ---------------------------------------------------------------------------
__global__ __launch_bounds__(256, 2)
void hgemm_kernel(const __half* __restrict__ A2, const __half* __restrict__ B,
                  float* __restrict__ C, int N, const float* __restrict__ bias)
{
    extern __shared__ __align__(1024) char smem[];
    const uint32_t su = smem_u32_of(smem);
    const int tid  = threadIdx.x;
    const int wid  = tid >> 5;
    const int lane = tid & 31;
    const int m0 = blockIdx.y * 128;
    const int n0 = blockIdx.x * 128;

    GemmFrag F;
    gemm_mainloop(A2, B, su, m0, n0, F);

    const int mwarp = (wid >> 2) * 64;
    const int nwarp = (wid & 3) * 32;
    const int mrow = lane >> 2;
    const int ncol = (lane & 3) * 2;
#pragma unroll
    for (int mf = 0; mf < 4; mf++) {
#pragma unroll
        for (int nf = 0; nf < 4; nf++) {
            int gm = m0 + mwarp + mf * 16 + mrow;
            int gn = n0 + nwarp + nf * 8 + ncol;
            float b0 = 0.f, b1 = 0.f;
            if (bias != nullptr) { b0 = bias[gn]; b1 = bias[gn + 1]; }
            float2 lo = make_float2(F.acc[mf][nf][0] + b0, F.acc[mf][nf][1] + b1);
            float2 hi = make_float2(F.acc[mf][nf][2] + b0, F.acc[mf][nf][3] + b1);
            *reinterpret_cast<float2*>(C + (size_t)gm * N + gn)       = lo;
            *reinterpret_cast<float2*>(C + (size_t)(gm + 8) * N + gn) = hi;
        }
    }
}

// ---------------------------------------------------------------------------
// Fused QKV GEMM + per-head RMSNorm + RoPE + fp16 epilogue.
//   cols [0,2048)    -> q heads: rmsnorm+rope -> qh/ql (fp16 hi/lo)
//   cols [2048,2560) -> k heads: rmsnorm+rope -> kh (fp16 single)
//   cols [2560,3072) -> v: fp16 single -> vh
// ---------------------------------------------------------------------------
__global__ __launch_bounds__(256, 2)
void qkv_gemm_kernel(const __half* __restrict__ A2, const __half* __restrict__ B,
                     const float* __restrict__ cosp, const float* __restrict__ sinp,
                     __half* __restrict__ qh, __half* __restrict__ ql,
                     __half* __restrict__ kh, __half* __restrict__ vh)
{
    extern __shared__ __align__(1024) char smem[];
    const uint32_t su = smem_u32_of(smem);
    const int tid  = threadIdx.x;
    const int wid  = tid >> 5;
    const int lane = tid & 31;
    const int m0 = blockIdx.y * 128;
    const int n0 = blockIdx.x * 128;

    GemmFrag F;
    gemm_mainloop(A2, B, su, m0, n0, F);

    const int mwarp = (wid >> 2) * 64;
    const int nwarp = (wid & 3) * 32;
    const int mrow = lane >> 2;
    const int ncol = (lane & 3) * 2;

    if (n0 >= 2560) {
        // V region: single fp16
#pragma unroll
        for (int mf = 0; mf < 4; mf++)
#pragma unroll
            for (int nf = 0; nf < 4; nf++) {
                int gm = m0 + mwarp + mf * 16 + mrow;
                int gn = n0 - 2560 + nwarp + nf * 8 + ncol;
                store2h(vh, (size_t)gm * 512 + gn,       F.acc[mf][nf][0], F.acc[mf][nf][1]);
                store2h(vh, (size_t)(gm + 8) * 512 + gn, F.acc[mf][nf][2], F.acc[mf][nf][3]);
            }
        return;
    }

    // ---- Q/K region: RMSNorm + RoPE, all in-CTA ----
    __syncthreads();   // pipeline smem no longer needed; safe to reuse
    const int NP = 132;
    float* ntile = reinterpret_cast<float*>(smem);     // [128][132] fp32
    float* ssqp  = ntile + 128 * NP;                   // [4][128]
    float* rmsv  = ssqp + 512;                         // [128]

#pragma unroll
    for (int mf = 0; mf < 4; mf++) {
        int lr0 = mwarp + mf * 16 + mrow;
        int lr1 = lr0 + 8;
        float p0 = 0.f, p1 = 0.f;
#pragma unroll
        for (int nf = 0; nf < 4; nf++) {
            int cc = nwarp + nf * 8 + ncol;
            float a0 = F.acc[mf][nf][0], a1 = F.acc[mf][nf][1];
            float a2 = F.acc[mf][nf][2], a3 = F.acc[mf][nf][3];
            ntile[lr0 * NP + cc]     = a0;
            ntile[lr0 * NP + cc + 1] = a1;
            ntile[lr1 * NP + cc]     = a2;
            ntile[lr1 * NP + cc + 1] = a3;
            p0 += a0 * a0 + a1 * a1;
            p1 += a2 * a2 + a3 * a3;
        }
        p0 += __shfl_xor_sync(0xffffffffu, p0, 1);
        p0 += __shfl_xor_sync(0xffffffffu, p0, 2);
        p1 += __shfl_xor_sync(0xffffffffu, p1, 1);
        p1 += __shfl_xor_sync(0xffffffffu, p1, 2);
        if ((lane & 3) == 0) {
            ssqp[(wid & 3) * 128 + lr0] = p0;
            ssqp[(wid & 3) * 128 + lr1] = p1;
        }
    }
    __syncthreads();
    if (tid < 128) {
        float s = ssqp[tid] + ssqp[128 + tid] + ssqp[256 + tid] + ssqp[384 + tid];
        rmsv[tid] = rsqrtf(s * (1.0f / 128.0f) + 1.1920929e-7f);
    }
    __syncthreads();

    // RoPE + store: 2 threads per row, 32 dims each half
    {
        int r = tid >> 1;
        int dbase = (tid & 1) * 32;
        int gm = m0 + r;
        int t  = gm & (SEQ - 1);
        float rm = rmsv[r];
        const bool isq = (n0 < 2048);
        size_t stride = isq ? 2048 : 512;
        int colbase = isq ? n0 : (n0 - 2048);
        size_t rowoff = (size_t)gm * stride + colbase;
        const float* crow = cosp + t * HALF;
        const float* srow = sinp + t * HALF;
        const float* nrow = ntile + r * NP;
#pragma unroll 4
        for (int j = 0; j < 32; j += 2) {
            int d = dbase + j;
            float v0a = nrow[d]      * rm, v1a = nrow[d + 64] * rm;
            float v0b = nrow[d + 1]  * rm, v1b = nrow[d + 65] * rm;
            float ca = crow[d],     sa = srow[d];
            float cb = crow[d + 1], sb = srow[d + 1];
            float y0 = v0a * ca - v1a * sa, y1 = v0b * cb - v1b * sb;
            float y2 = v0a * sa + v1a * ca, y3 = v0b * sb + v1b * cb;
            if (isq) {
                split_store2h(qh, ql, rowoff + d,      y0, y1);
                split_store2h(qh, ql, rowoff + 64 + d, y2, y3);
            } else {
                store2h(kh, rowoff + d,      y0, y1);
                store2h(kh, rowoff + 64 + d, y2, y3);
            }
        }
    }
}

// ---------------------------------------------------------------------------
// fp32 -> (hi, lo) fp16 split. src [M, 2048] -> dst [M, 4096] ([hi|lo]).
// ---------------------------------------------------------------------------
__global__ void split2048_kernel(const float* __restrict__ src, __half* __restrict__ dst)
{
    int i = blockIdx.x * 256 + threadIdx.x;
    float4 v = reinterpret_cast<const float4*>(src)[i];
    int e = i * 4;
    int m = e >> 11;
    int k = e & 2047;
    __half* d = dst + (size_t)m * 4096 + k;
    __half h0 = __float2half(v.x), h1 = __float2half(v.y);
    __half h2 = __float2half(v.z), h3 = __float2half(v.w);
    d[0] = h0; d[1] = h1; d[2] = h2; d[3] = h3;
    d[2048] = __float2half(v.x - __half2float(h0));
    d[2049] = __float2half(v.y - __half2float(h1));
    d[2050] = __float2half(v.z - __half2float(h2));
    d[2051] = __float2half(v.w - __half2float(h3));
}

// ---------------------------------------------------------------------------
// Transposed fp16 convert of W [2048, N] into dst columns [nbase, nbase+N),
// K-major [n][2048].
// ---------------------------------------------------------------------------
__device__ __forceinline__ void tconv_body(const float* __restrict__ W,
                                           __half* __restrict__ dst,
                                           int N, int nbase, int bx, int by)
{
    __shared__ float tl[32][33];
    int tx = threadIdx.x, ty = threadIdx.y;
    int n0 = bx * 32, k0 = by * 32;
#pragma unroll
    for (int j = 0; j < 4; j++)
        tl[ty + j * 8][tx] = W[(size_t)(k0 + ty + j * 8) * N + n0 + tx];
    __syncthreads();
#pragma unroll
    for (int j = 0; j < 4; j++) {
        int n = nbase + n0 + ty + j * 8;
        int k = k0 + tx;
        dst[(size_t)n * 2048 + k] = __float2half(tl[tx][ty + j * 8]);
    }
}

__global__ void tconv_qkv_kernel(const float* __restrict__ Wq, const float* __restrict__ Wk,
                                 const float* __restrict__ Wv, __half* __restrict__ dst)
{
    int z = blockIdx.z;
    const float* W = (z == 0) ? Wq : (z == 1) ? Wk : Wv;
    int N     = (z == 0) ? 2048 : 512;
    int nbase = (z == 0) ? 0 : (z == 1) ? 2048 : 2560;
    if ((int)blockIdx.x * 32 >= N) return;
    tconv_body(W, dst, N, nbase, blockIdx.x, blockIdx.y);
}

__global__ void tconv_wo_kernel(const float* __restrict__ W, __half* __restrict__ dst)
{
    tconv_body(W, dst, 2048, 0, blockIdx.x, blockIdx.y);
}

// ---------------------------------------------------------------------------
// fp16 HMMA flash attention, causal, GQA.
//   S = qh*k + ql*k (2 terms).  O += ph*v + pl*v (2 terms).
// Smem: Qhi 32K | Qlo 32K | K 2st 32K | V 2st 32K | Phi 16K | Plo 16K = 160K
// ---------------------------------------------------------------------------
#define FA_QHI 0
#define FA_QLO 32768
#define FA_K   65536
#define FA_V   98304
#define FA_PHI 131072
#define FA_PLO 147456
#define FA_SMEM 163840

__global__ __launch_bounds__(256, 1)
void flash_hmma_kernel(const __half* __restrict__ qh, const __half* __restrict__ ql,
                       const __half* __restrict__ kh, const __half* __restrict__ vh,
                       __half* __restrict__ x2)
{
    extern __shared__ __align__(1024) char smem[];
    const uint32_t su = smem_u32_of(smem);
    const int tid  = threadIdx.x;
    const int wid  = tid >> 5;
    const int lane = tid & 31;

    const int qt = (int)gridDim.x - 1 - (int)blockIdx.x;   // long CTAs first
    const int bh = blockIdx.y;
    const int b  = bh >> 4;
    const int h  = bh & 15;
    const int hkv = h >> 2;
    const int q0 = qt * 128;
    const float scale = 0.08838834764831845f;   // 1/sqrt(128)

    const __half* qhb = qh + (size_t)b * SEQ * QW + h * HDIM;
    const __half* qlb = ql + (size_t)b * SEQ * QW + h * HDIM;
    const __half* khb = kh + (size_t)b * SEQ * KW + hkv * HDIM;
    const __half* vhb = vh + (size_t)b * SEQ * KW + hkv * HDIM;

    for (int i = tid; i < 128 * 16; i += 256) {
        int r = i >> 4, c = i & 15;
        *reinterpret_cast<uint4*>(smem + FA_QHI + SW256(r, c)) =
            *reinterpret_cast<const uint4*>(qhb + (size_t)(q0 + r) * QW + c * 8);
        *reinterpret_cast<uint4*>(smem + FA_QLO + SW256(r, c)) =
            *reinterpret_cast<const uint4*>(qlb + (size_t)(q0 + r) * QW + c * 8);
    }

    const int asel = lane >> 3;
    const int arow = (lane & 7) + ((asel & 1) << 3);
    const int akc  = asel >> 1;
    const int brow = (lane & 7) + ((asel >> 1) << 3);
    const int bkc  = asel & 1;
    const int qrow_s = wid * 16 + arow;

    float o[16][4];
#pragma unroll
    for (int g = 0; g < 16; g++)
#pragma unroll
        for (int e = 0; e < 4; e++) o[g][e] = 0.f;
    float m0 = -1e30f, m1 = -1e30f, l0 = 0.f, l1 = 0.f;

    const int ntiles = 2 * qt + 2;

    auto issueKV = [&](int kt) {
        int k0 = kt * 64;
        uint32_t kb = su + FA_K + (uint32_t)(kt & 1) * 16384u;
        uint32_t vb = su + FA_V + (uint32_t)(kt & 1) * 16384u;
#pragma unroll
        for (int i = 0; i < 4; i++) {
            int id = tid + i * 256;
            int r = id >> 4, c = id & 15;
            size_t go = (size_t)(k0 + r) * KW + c * 8;
            uint32_t so = SW256(r, c);
            cp_async16(kb + so, khb + go);
            cp_async16(vb + so, vhb + go);
        }
        cp_commit();
    };

    issueKV(0);

    const int r0g = q0 + wid * 16 + (lane >> 2);
    const int r1g = r0g + 8;
    const int pr0 = wid * 16 + (lane >> 2);
    const int pr1 = pr0 + 8;

    for (int kt = 0; kt < ntiles; ++kt) {
        if (kt + 1 < ntiles) { issueKV(kt + 1); cp_wait1(); }
        else                 { cp_wait0(); }
        __syncthreads();

        uint32_t kb = su + FA_K + (uint32_t)(kt & 1) * 16384u;
        uint32_t vb = su + FA_V + (uint32_t)(kt & 1) * 16384u;

        // ---- S = QK^T (fp16, 2 terms) ----
        float s[8][4];
#pragma unroll
        for (int t = 0; t < 8; t++)
#pragma unroll
            for (int e = 0; e < 4; e++) s[t][e] = 0.f;

#pragma unroll
        for (int d = 0; d < 8; ++d) {
            uint32_t ah[4], al[4];
            ldmatrix_x4(ah, su + FA_QHI + SW256(qrow_s, d * 2 + akc));
            ldmatrix_x4(al, su + FA_QLO + SW256(qrow_s, d * 2 + akc));
#pragma unroll
            for (int j = 0; j < 4; ++j) {
                int R = j * 16 + brow;
                uint32_t kf[4];
                ldmatrix_x4(kf, kb + SW256(R, d * 2 + bkc));
                mma_fp16(s[2 * j],     ah, kf[0], kf[1]);
                mma_fp16(s[2 * j + 1], ah, kf[2], kf[3]);
                mma_fp16(s[2 * j],     al, kf[0], kf[1]);
                mma_fp16(s[2 * j + 1], al, kf[2], kf[3]);
            }
        }

        const int k0 = kt * 64;
        const bool dm = (kt >= 2 * qt);
        float mx0 = -1e30f, mx1 = -1e30f;
#pragma unroll
        for (int t = 0; t < 8; t++) {
            int c0 = k0 + t * 8 + (lane & 3) * 2;
            s[t][0] *= scale; s[t][1] *= scale; s[t][2] *= scale; s[t][3] *= scale;
            if (dm) {
                if (c0     > r0g) s[t][0] = -1e30f;
                if (c0 + 1 > r0g) s[t][1] = -1e30f;
                if (c0     > r1g) s[t][2] = -1e30f;
                if (c0 + 1 > r1g) s[t][3] = -1e30f;
            }
            mx0 = fmaxf(mx0, fmaxf(s[t][0], s[t][1]));
            mx1 = fmaxf(mx1, fmaxf(s[t][2], s[t][3]));
        }
        mx0 = fmaxf(mx0, __shfl_xor_sync(0xffffffffu, mx0, 1));
        mx0 = fmaxf(mx0, __shfl_xor_sync(0xffffffffu, mx0, 2));
        mx1 = fmaxf(mx1, __shfl_xor_sync(0xffffffffu, mx1, 1));
        mx1 = fmaxf(mx1, __shfl_xor_sync(0xffffffffu, mx1, 2));

        float mn0 = fmaxf(m0, mx0), mn1 = fmaxf(m1, mx1);
        float a0 = __expf(m0 - mn0), a1 = __expf(m1 - mn1);
        m0 = mn0; m1 = mn1;

        // ---- P = exp(S - m); split to fp16 hi/lo in smem ----
        float rs0 = 0.f, rs1 = 0.f;
#pragma unroll
        for (int t = 0; t < 8; t++) {
            float p0 = __expf(s[t][0] - m0);
            float p1 = __expf(s[t][1] - m0);
            float p2 = __expf(s[t][2] - m1);
            float p3 = __expf(s[t][3] - m1);
            rs0 += p0 + p1; rs1 += p2 + p3;
            __half h0 = __float2half(p0), h1 = __float2half(p1);
            __half h2 = __float2half(p2), h3 = __float2half(p3);
            __half2 hp01 = {h0, h1}, hp23 = {h2, h3};
            __half2 lp01 = {__float2half(p0 - __half2float(h0)),
                            __float2half(p1 - __half2float(h1))};
            __half2 lp23 = {__float2half(p2 - __half2float(h2)),
                            __float2half(p3 - __half2float(h3))};
            uint32_t o0 = (uint32_t)(pr0 * 128 + (((t) ^ (pr0 & 7)) << 4) + (lane & 3) * 4);
            uint32_t o1 = (uint32_t)(pr1 * 128 + (((t) ^ (pr1 & 7)) << 4) + (lane & 3) * 4);
            *reinterpret_cast<__half2*>(smem + FA_PHI + o0) = hp01;
            *reinterpret_cast<__half2*>(smem + FA_PHI + o1) = hp23;
            *reinterpret_cast<__half2*>(smem + FA_PLO + o0) = lp01;
            *reinterpret_cast<__half2*>(smem + FA_PLO + o1) = lp23;
        }
        rs0 += __shfl_xor_sync(0xffffffffu, rs0, 1);
        rs0 += __shfl_xor_sync(0xffffffffu, rs0, 2);
        rs1 += __shfl_xor_sync(0xffffffffu, rs1, 1);
        rs1 += __shfl_xor_sync(0xffffffffu, rs1, 2);
        l0 = l0 * a0 + rs0;
        l1 = l1 * a1 + rs1;

#pragma unroll
        for (int g = 0; g < 16; g++) {
            o[g][0] *= a0; o[g][1] *= a0; o[g][2] *= a1; o[g][3] *= a1;
        }
        __syncwarp();

        // ---- O += (ph + pl) * v ----
        const int vrow0 = (lane & 7) + ((asel & 1) << 3);
        const int vkc   = asel >> 1;
#pragma unroll
        for (int ks = 0; ks < 4; ++ks) {
            uint32_t ph[4], pl[4];
            ldmatrix_x4(ph, su + FA_PHI + SW128(qrow_s, ks * 2 + akc));
            ldmatrix_x4(pl, su + FA_PLO + SW128(qrow_s, ks * 2 + akc));
            int vr = ks * 16 + vrow0;
#pragma unroll
            for (int g = 0; g < 8; ++g) {
                uint32_t vf[4];
                ldmatrix_x4_trans(vf, vb + SW256(vr, g * 2 + vkc));
                mma_fp16(o[2 * g],     ph, vf[0], vf[1]);
                mma_fp16(o[2 * g + 1], ph, vf[2], vf[3]);
                mma_fp16(o[2 * g],     pl, vf[0], vf[1]);
                mma_fp16(o[2 * g + 1], pl, vf[2], vf[3]);
            }
        }
        __syncthreads();
    }

    float inv0 = 1.0f / l0, inv1 = 1.0f / l1;
    int row0 = b * SEQ + q0 + wid * 16 + (lane >> 2);
    int row1 = row0 + 8;
#pragma unroll
    for (int g = 0; g < 16; g++) {
        int col = h * HDIM + g * 8 + (lane & 3) * 2;
        float y0 = o[g][0] * inv0, y1 = o[g][1] * inv0;
        float y2 = o[g][2] * inv1, y3 = o[g][3] * inv1;
        split_store2h(x2, x2 + 2048, (size_t)row0 * 4096 + col, y0, y1);
        split_store2h(x2, x2 + 2048, (size_t)row1 * 4096 + col, y2, y3);
    }
}

// ---------------------------------------------------------------------------
// Launch
// ---------------------------------------------------------------------------
extern "C" void kernel_launch(void* const* d_in, const int* in_sizes, int n_in,
                              void* d_out, int out_size)
{
    const float* x    = (const float*)d_in[0];
    const float* cosp = (const float*)d_in[1];
    const float* sinp = (const float*)d_in[2];
    const float* Wq   = (const float*)d_in[3];
    const float* Wk   = (const float*)d_in[4];
    const float* Wv   = (const float*)d_in[5];
    const float* Wo   = (const float*)d_in[6];
    const float* bo   = (const float*)d_in[7];
    float* out = (float*)d_out;

    __half *x2, *wqkv, *wo2, *qh, *ql, *kh, *vh;
    cudaGetSymbolAddress((void**)&x2,   g_x2);
    cudaGetSymbolAddress((void**)&wqkv, g_wqkv);
    cudaGetSymbolAddress((void**)&wo2,  g_wo2);
    cudaGetSymbolAddress((void**)&qh,   g_qh);
    cudaGetSymbolAddress((void**)&ql,   g_ql);
    cudaGetSymbolAddress((void**)&kh,   g_kh);
    cudaGetSymbolAddress((void**)&vh,   g_vh);

    cudaFuncSetAttribute(hgemm_kernel, cudaFuncAttributeMaxDynamicSharedMemorySize, HG_SMEM);
    cudaFuncSetAttribute(qkv_gemm_kernel, cudaFuncAttributeMaxDynamicSharedMemorySize, HG_SMEM);
    cudaFuncSetAttribute(flash_hmma_kernel, cudaFuncAttributeMaxDynamicSharedMemorySize, FA_SMEM);

    // prep (order keeps qkv_gemm as our 4th launch for ncu -s 5)
    tconv_qkv_kernel<<<dim3(64, 64, 3), dim3(32, 8)>>>(Wq, Wk, Wv, wqkv);
    split2048_kernel<<<MROWS * CDIM / 4 / 256, 256>>>(x, x2);
    tconv_wo_kernel<<<dim3(64, 64), dim3(32, 8)>>>(Wo, wo2);

    // Fused QKV projection + rmsnorm + rope (fp16 2-segment GEMM)
    qkv_gemm_kernel<<<dim3(3072 / 128, MROWS / 128), 256, HG_SMEM>>>(
        x2, wqkv, cosp, sinp, qh, ql, kh, vh);

    // fp16 flash attention (writes fp16 split output into x2)
    dim3 ga(SEQ / 128, BATCH * NHEAD);
    flash_hmma_kernel<<<ga, 256, FA_SMEM>>>(qh, ql, kh, vh, x2);

    // output projection + bias (fp16 2-segment GEMM)
    hgemm_kernel<<<dim3(QW / 128, MROWS / 128), 256, HG_SMEM>>>(x2, wo2, out, QW, bo);
}